// round 11
// baseline (speedup 1.0000x reference)
#include <cuda_runtime.h>
#include <cuda_bf16.h>
#include <cstdint>
#include <math.h>

#define BF 256
#define NT 256

// ---------------------------------------------------------------------------
// Static scratch. All intermediates bf16.
// ---------------------------------------------------------------------------
__device__ __align__(16) __nv_bfloat16 g_x0[(size_t)BF*NT*27*16];
__device__ __align__(16) __nv_bfloat16 g_x1[(size_t)BF*NT*9*32];
__device__ __align__(16) __nv_bfloat16 g_x2[(size_t)BF*NT*3*64];
__device__ __align__(16) __nv_bfloat16 g_xT[(size_t)NT*BF*128];
__device__ __align__(16) __nv_bfloat16 g_G[(size_t)2*65536*512];
__device__ __align__(16) __nv_bfloat16 g_hcat[(size_t)BF*65536];
__device__ __align__(16) float g_fc1part[(size_t)128*256*128];
__device__ __align__(16) float g_z1[(size_t)256*128];
__device__ __align__(16) __nv_bfloat16 g_wT1[9*32*16];
__device__ __align__(16) __nv_bfloat16 g_wT2[9*64*32];
__device__ __align__(16) __nv_bfloat16 g_wT3[9*128*64];
__device__ __align__(16) __nv_bfloat16 g_Wihb16[(size_t)2*512*128];
__device__ __align__(16) __nv_bfloat16 g_fc1wb16[(size_t)128*65536];

// ---------------------------------------------------------------------------
// helpers
// ---------------------------------------------------------------------------
__device__ __forceinline__ uint32_t packbf(float lo, float hi)
{
    __nv_bfloat162 h = __floats2bfloat162_rn(lo, hi);
    return *(uint32_t*)&h;
}
__device__ __forceinline__ void mma_bf16(float* d, const uint32_t* a, const uint32_t* b)
{
    asm("mma.sync.aligned.m16n8k16.row.col.f32.bf16.bf16.f32 "
        "{%0,%1,%2,%3}, {%4,%5,%6,%7}, {%8,%9}, {%0,%1,%2,%3};"
        : "+f"(d[0]), "+f"(d[1]), "+f"(d[2]), "+f"(d[3])
        : "r"(a[0]), "r"(a[1]), "r"(a[2]), "r"(a[3]), "r"(b[0]), "r"(b[1]));
}
__device__ __forceinline__ uint32_t smem_u32(const void* p)
{
    return (uint32_t)__cvta_generic_to_shared(p);
}
__device__ __forceinline__ void cp16(uint32_t dst, const void* src)
{
    asm volatile("cp.async.cg.shared.global [%0], [%1], 16;" :: "r"(dst), "l"(src));
}
__device__ __forceinline__ void cp16z(uint32_t dst, const void* src)
{
    asm volatile("cp.async.cg.shared.global [%0], [%1], 16, 0;" :: "r"(dst), "l"(src));
}
__device__ __forceinline__ void cp_commit() { asm volatile("cp.async.commit_group;"); }
__device__ __forceinline__ void cp_wait0()  { asm volatile("cp.async.wait_group 0;"); }

// ---------------------------------------------------------------------------
// Prep kernels
// ---------------------------------------------------------------------------
__global__ void wtrans_k(const float* __restrict__ w1, const float* __restrict__ w2,
                         const float* __restrict__ w3)
{
    int idx = blockIdx.x*256 + threadIdx.x;
    const float* w; __nv_bfloat16* wT; int CIN, COUT;
    if (idx < 4608)        { w = w1; wT = g_wT1; CIN = 16; COUT = 32; }
    else if (idx < 23040)  { w = w2; wT = g_wT2; CIN = 32; COUT = 64; idx -= 4608; }
    else if (idx < 96768)  { w = w3; wT = g_wT3; CIN = 64; COUT = 128; idx -= 23040; }
    else return;
    int ci  = idx % CIN;
    int r   = idx / CIN;
    int co  = r % COUT;
    int tap = r / COUT;
    wT[idx] = __float2bfloat16(w[(co*CIN + ci)*9 + tap]);
}

__global__ void prep_bf16_k(const float* __restrict__ Wihf, const float* __restrict__ Wihb,
                            const float* __restrict__ fc1w)
{
    const size_t total = 131072 + 8388608;
    for (size_t i = (size_t)blockIdx.x*256 + threadIdx.x; i < total;
         i += (size_t)gridDim.x*256) {
        if (i < 65536)        g_Wihb16[i] = __float2bfloat16(Wihf[i]);
        else if (i < 131072)  g_Wihb16[i] = __float2bfloat16(Wihb[i-65536]);
        else                  g_fc1wb16[i-131072] = __float2bfloat16(fc1w[i-131072]);
    }
}

// ---------------------------------------------------------------------------
// conv0: CIN=1 -> 16, direct. out NHWC bf16 [bf][t][27][16].
// ---------------------------------------------------------------------------
__global__ void conv0_k(const float* __restrict__ audio, const float* __restrict__ w,
                        const float* __restrict__ bias, __nv_bfloat16* __restrict__ out)
{
    __shared__ float wsm[9][16];
    __shared__ float bsm[16];
    int tid = threadIdx.x;
    if (tid < 144) wsm[tid % 9][tid / 9] = w[tid];
    if (tid < 16)  bsm[tid] = bias[tid];
    __syncthreads();

    size_t idx = (size_t)blockIdx.x*256 + tid;
    int wo = (int)(idx % 27);
    size_t r = idx / 27;
    int t  = (int)(r % NT);
    int bf = (int)(r / NT);

    float acc[16];
    #pragma unroll
    for (int co = 0; co < 16; co++) acc[co] = bsm[co];

    #pragma unroll
    for (int kh = 0; kh < 3; kh++) {
        int ti = t + kh - 1;
        if (ti < 0 || ti >= NT) continue;
        #pragma unroll
        for (int kw = 0; kw < 3; kw++) {
            int wc = 3*wo + kw - 1;
            if (wc < 0 || wc >= 81) continue;
            float v = audio[((size_t)bf*NT + ti)*81 + wc];
            #pragma unroll
            for (int co = 0; co < 16; co++) acc[co] += v * wsm[kh*3+kw][co];
        }
    }
    uint32_t* o = (uint32_t*)(out + idx*16);
    #pragma unroll
    for (int q = 0; q < 8; q++)
        o[q] = packbf(fmaxf(acc[q*2+0], 0.f), fmaxf(acc[q*2+1], 0.f));
}

// ---------------------------------------------------------------------------
// Conv, bf16 mma, single tile load per block (unchanged from R10).
// ---------------------------------------------------------------------------
template<int CIN,int COUT,int WIN,int WOUT,bool TOUT>
__global__ void conv_mma_k(const __nv_bfloat16* __restrict__ x,
                           const __nv_bfloat16* __restrict__ wT,
                           const float* __restrict__ bias,
                           __nv_bfloat16* __restrict__ out)
{
    constexpr int CU  = CIN/2;
    constexpr int LDT = WIN*CU + 4;
    constexpr int LDB = CU + 4;
    constexpr int NWN = COUT/32, WMW = 8/NWN, MFR = 128/WMW/16;
    constexpr int NK16 = CIN/16;
    extern __shared__ uint32_t sm[];
    uint32_t* At = sm;
    uint32_t* Bt = sm + 130*LDT;

    const int tid  = threadIdx.x;
    const int lane = tid & 31;
    const int wid  = tid >> 5;
    const int g    = lane >> 2, tq = lane & 3;
    const int wm0  = (wid % WMW) * (128/WMW);
    const int wn0  = (wid / WMW) * 32;
    const int t0   = blockIdx.x * 128;
    const int bf   = blockIdx.y;

    constexpr int ACH = WIN*CU/4;
    for (int l = tid; l < 130*ACH; l += 256) {
        int row = l / ACH, ch = l % ACH;
        int t_in = t0 + row - 1;
        uint32_t dst = smem_u32(At + row*LDT + ch*4);
        const __nv_bfloat16* src = x + ((size_t)bf*NT + (t_in < 0 ? 0 : (t_in >= NT ? NT-1 : t_in)))*WIN*CIN + ch*8;
        if (t_in >= 0 && t_in < NT) cp16(dst, src);
        else                        cp16z(dst, src);
    }
    constexpr int BCH = CU/4;
    for (int l = tid; l < 9*COUT*BCH; l += 256) {
        int r = l / BCH, ch = l % BCH;
        cp16(smem_u32(Bt + r*LDB + ch*4), wT + (size_t)r*CIN + ch*8);
    }
    cp_commit();
    cp_wait0();
    __syncthreads();

    float bv[4][2];
    #pragma unroll
    for (int fj = 0; fj < 4; fj++) {
        int co0 = wn0 + fj*8 + 2*tq;
        bv[fj][0] = bias[co0]; bv[fj][1] = bias[co0+1];
    }

    #pragma unroll 1
    for (int wo = 0; wo < WOUT; wo++) {
        float acc[MFR][4][4];
        #pragma unroll
        for (int i = 0; i < MFR; i++)
            #pragma unroll
            for (int j = 0; j < 4; j++)
                #pragma unroll
                for (int q = 0; q < 4; q++) acc[i][j][q] = 0.f;

        #pragma unroll
        for (int kh = 0; kh < 3; kh++) {
            #pragma unroll
            for (int kw = 0; kw < 3; kw++) {
                const int wc = 3*wo + kw - 1;
                if (wc < 0 || wc >= WIN) continue;
                const uint32_t* Btap = Bt + (size_t)(kh*3+kw)*COUT*LDB;
                #pragma unroll
                for (int k16 = 0; k16 < NK16; k16++) {
                    const int kp = k16*8;
                    const int ac = wc*CU + kp;
                    uint32_t a[MFR][4], b[4][2];
                    #pragma unroll
                    for (int fi = 0; fi < MFR; fi++) {
                        int r = wm0 + fi*16 + g + kh;
                        a[fi][0] = At[(r  )*LDT + ac + tq];
                        a[fi][1] = At[(r+8)*LDT + ac + tq];
                        a[fi][2] = At[(r  )*LDT + ac + tq + 4];
                        a[fi][3] = At[(r+8)*LDT + ac + tq + 4];
                    }
                    #pragma unroll
                    for (int fj = 0; fj < 4; fj++) {
                        int cn = wn0 + fj*8 + g;
                        b[fj][0] = Btap[cn*LDB + kp + tq];
                        b[fj][1] = Btap[cn*LDB + kp + tq + 4];
                    }
                    #pragma unroll
                    for (int fi = 0; fi < MFR; fi++)
                        #pragma unroll
                        for (int fj = 0; fj < 4; fj++)
                            mma_bf16(acc[fi][fj], a[fi], b[fj]);
                }
            }
        }

        #pragma unroll
        for (int fj = 0; fj < 4; fj++) {
            int co0 = wn0 + fj*8 + 2*tq;
            #pragma unroll
            for (int fi = 0; fi < MFR; fi++) {
                #pragma unroll
                for (int p = 0; p < 2; p++) {
                    int m = wm0 + fi*16 + g + p*8;
                    uint32_t v = packbf(fmaxf(acc[fi][fj][p*2+0] + bv[fj][0], 0.f),
                                        fmaxf(acc[fi][fj][p*2+1] + bv[fj][1], 0.f));
                    size_t base;
                    if (TOUT) base = ((size_t)(t0+m)*BF + bf)*COUT + co0;
                    else      base = (((size_t)bf*NT + (t0+m))*WOUT + wo)*COUT + co0;
                    *(uint32_t*)(out + base) = v;
                }
            }
        }
    }
}

// ---------------------------------------------------------------------------
// Input-projection GEMM (unchanged from R10).
// ---------------------------------------------------------------------------
__global__ void gemm_xw_k(const __nv_bfloat16* __restrict__ X,
                          const float* __restrict__ bihf, const float* __restrict__ bhhf,
                          const float* __restrict__ bihb, const float* __restrict__ bhhb)
{
    const int dir = blockIdx.z;
    const __nv_bfloat16* W = g_Wihb16 + (size_t)dir*65536;
    const float* b1 = dir ? bihb : bihf;
    const float* b2 = dir ? bhhb : bhhf;
    __nv_bfloat16* out = g_G + (size_t)dir*65536*512;

    __shared__ uint32_t As[2][128][20];
    __shared__ uint32_t Bs[2][128][20];

    const int tid  = threadIdx.x;
    const int lane = tid & 31;
    const int wid  = tid >> 5;
    const int g    = lane >> 2, tq = lane & 3;
    const int wm0  = (wid & 1) * 64;
    const int wn0  = (wid >> 1) * 32;
    const int m0   = blockIdx.y * 128, n0 = blockIdx.x * 128;

    const int l = tid, l2 = 256 + tid;
    const int ma = l >> 2, ka = l & 3, mb = l2 >> 2, kb = l2 & 3;

    float acc[4][4][4];
    #pragma unroll
    for (int i = 0; i < 4; i++)
        #pragma unroll
        for (int j = 0; j < 4; j++)
            #pragma unroll
            for (int q = 0; q < 4; q++) acc[i][j][q] = 0.f;

    cp16(smem_u32(&As[0][ma][ka*4]), X + (size_t)(m0+ma)*128 + ka*8);
    cp16(smem_u32(&As[0][mb][kb*4]), X + (size_t)(m0+mb)*128 + kb*8);
    cp16(smem_u32(&Bs[0][ma][ka*4]), W + (size_t)(n0+ma)*128 + ka*8);
    cp16(smem_u32(&Bs[0][mb][kb*4]), W + (size_t)(n0+mb)*128 + kb*8);
    cp_commit();
    cp_wait0();
    __syncthreads();

    for (int it = 0; it < 4; it++) {
        const int b = it & 1;
        if (it < 3) {
            int kt = (it+1)*32;
            cp16(smem_u32(&As[b^1][ma][ka*4]), X + (size_t)(m0+ma)*128 + kt + ka*8);
            cp16(smem_u32(&As[b^1][mb][kb*4]), X + (size_t)(m0+mb)*128 + kt + kb*8);
            cp16(smem_u32(&Bs[b^1][ma][ka*4]), W + (size_t)(n0+ma)*128 + kt + ka*8);
            cp16(smem_u32(&Bs[b^1][mb][kb*4]), W + (size_t)(n0+mb)*128 + kt + kb*8);
            cp_commit();
        }
        #pragma unroll
        for (int k16 = 0; k16 < 2; k16++) {
            const int kp = k16*8;
            uint32_t a[4][4], bb[4][2];
            #pragma unroll
            for (int fi = 0; fi < 4; fi++) {
                int r = wm0 + fi*16;
                a[fi][0] = As[b][r+g  ][kp+tq];
                a[fi][1] = As[b][r+g+8][kp+tq];
                a[fi][2] = As[b][r+g  ][kp+tq+4];
                a[fi][3] = As[b][r+g+8][kp+tq+4];
            }
            #pragma unroll
            for (int fj = 0; fj < 4; fj++) {
                int cn = wn0 + fj*8 + g;
                bb[fj][0] = Bs[b][cn][kp+tq];
                bb[fj][1] = Bs[b][cn][kp+tq+4];
            }
            #pragma unroll
            for (int fi = 0; fi < 4; fi++)
                #pragma unroll
                for (int fj = 0; fj < 4; fj++)
                    mma_bf16(acc[fi][fj], a[fi], bb[fj]);
        }
        if (it < 3) cp_wait0();
        __syncthreads();
    }

    #pragma unroll
    for (int fj = 0; fj < 4; fj++) {
        int gate0 = n0 + wn0 + fj*8 + 2*tq;
        float bv0 = b1[gate0]   + b2[gate0];
        float bv1 = b1[gate0+1] + b2[gate0+1];
        #pragma unroll
        for (int fi = 0; fi < 4; fi++) {
            #pragma unroll
            for (int p = 0; p < 2; p++) {
                int m = m0 + wm0 + fi*16 + g + p*8;
                *(uint32_t*)(out + (size_t)m*512 + gate0) =
                    packbf(acc[fi][fj][p*2+0] + bv0, acc[fi][fj][p*2+1] + bv1);
            }
        }
    }
}

// ---------------------------------------------------------------------------
// LSTM recurrence: SINGLE CTA per (16-batch group, dir). NO cluster.
// All 512 gate rows of Whh live as bf16 mma fragments in registers
// (8 warps x 8 n-frags x 8 k-tiles x 2 = 128 regs/thread).
// Per step: 64 mma/warp -> zsm, sync, gate-update, sync. Grid (16, 2).
// ---------------------------------------------------------------------------
__device__ __forceinline__ float sigf(float x) { return 1.f / (1.f + expf(-x)); }

__global__ void __launch_bounds__(256,1)
lstm_k(const float* __restrict__ Whhf, const float* __restrict__ Whhb)
{
    __shared__ __nv_bfloat16 hbuf[2*16*136];   // [buf][batch][128+8]
    __shared__ float zsm[16][520];             // [batch][512 gates + pad]

    const int tid  = threadIdx.x;
    const int lane = tid & 31;
    const int w    = tid >> 5;
    const int g    = lane >> 2, tq = lane & 3;
    const int dir  = blockIdx.y;
    const int nb0  = blockIdx.x * 16;
    const float* Whh = dir ? Whhb : Whhf;
    const __nv_bfloat16* G = g_G + (size_t)dir*65536*512;

    // Whh fragments: warp w owns gate rows [w*64, w*64+64)
    uint32_t wb[8][8][2];
    #pragma unroll
    for (int fj = 0; fj < 8; fj++) {
        int grow = w*64 + fj*8 + g;
        const float* wr = Whh + (size_t)grow*128;
        #pragma unroll
        for (int kt = 0; kt < 8; kt++) {
            wb[fj][kt][0] = packbf(wr[kt*16 + 2*tq    ], wr[kt*16 + 2*tq + 1]);
            wb[fj][kt][1] = packbf(wr[kt*16 + 2*tq + 8], wr[kt*16 + 2*tq + 9]);
        }
    }

    {
        uint32_t* hz = (uint32_t*)hbuf;
        for (int idx = tid; idx < 2*16*136/2; idx += 256) hz[idx] = 0u;
    }
    __syncthreads();

    const int jj = tid & 127;          // hidden unit
    const int mh = (tid >> 7) * 8;     // batch sub-group (0 or 8)
    float c[8];
    #pragma unroll
    for (int i = 0; i < 8; i++) c[i] = 0.f;

    float Gc[8][4], Gn[8][4];
    {
        int t0 = dir ? 255 : 0;
        #pragma unroll
        for (int mm = 0; mm < 8; mm++)
            #pragma unroll
            for (int gt = 0; gt < 4; gt++)
                Gc[mm][gt] = __bfloat162float(G[((size_t)t0*256 + nb0 + mh + mm)*512 + gt*128 + jj]);
    }

    for (int s = 0; s < 256; s++) {
        const int t   = dir ? (255 - s) : s;
        const int cur = s & 1, nxt = cur ^ 1;

        // ---- phase A: Z[16][512] = h @ Whh^T, all gates in one CTA ----
        float acc[8][4];
        #pragma unroll
        for (int fj = 0; fj < 8; fj++)
            #pragma unroll
            for (int q = 0; q < 4; q++) acc[fj][q] = 0.f;

        const uint32_t* hb = (const uint32_t*)(hbuf + cur*16*136);  // stride 68 u32
        #pragma unroll
        for (int kt = 0; kt < 8; kt++) {
            const int kp = kt*8;
            uint32_t a[4];
            a[0] = hb[(g  )*68 + kp + tq];
            a[1] = hb[(g+8)*68 + kp + tq];
            a[2] = hb[(g  )*68 + kp + tq + 4];
            a[3] = hb[(g+8)*68 + kp + tq + 4];
            #pragma unroll
            for (int fj = 0; fj < 8; fj++)
                mma_bf16(acc[fj], a, wb[fj][kt]);
        }
        #pragma unroll
        for (int fj = 0; fj < 8; fj++) {
            int nloc = w*64 + fj*8 + 2*tq;
            *(float2*)&zsm[g  ][nloc] = make_float2(acc[fj][0], acc[fj][1]);
            *(float2*)&zsm[g+8][nloc] = make_float2(acc[fj][2], acc[fj][3]);
        }
        __syncthreads();

        // prefetch next step's G
        if (s < 255) {
            int tn = dir ? (254 - s) : (s + 1);
            #pragma unroll
            for (int mm = 0; mm < 8; mm++)
                #pragma unroll
                for (int gt = 0; gt < 4; gt++)
                    Gn[mm][gt] = __bfloat162float(G[((size_t)tn*256 + nb0 + mh + mm)*512 + gt*128 + jj]);
        }

        // ---- phase B: gate combine + state update (8 batches/thread) ----
        #pragma unroll
        for (int mm = 0; mm < 8; mm++) {
            int m = mh + mm;
            float ai = zsm[m][  0 + jj] + Gc[mm][0];
            float af = zsm[m][128 + jj] + Gc[mm][1];
            float ag = zsm[m][256 + jj] + Gc[mm][2];
            float ao = zsm[m][384 + jj] + Gc[mm][3];
            float iv = sigf(ai);
            float fv = sigf(af);
            float gv = tanhf(ag);
            float ov = sigf(ao);
            c[mm] = fv*c[mm] + iv*gv;
            float hv = ov * tanhf(c[mm]);
            __nv_bfloat16 hb16 = __float2bfloat16(hv);
            g_hcat[(size_t)(nb0+m)*65536 + t*256 + dir*128 + jj] = hb16;
            hbuf[(nxt*16 + m)*136 + jj] = hb16;
        }
        #pragma unroll
        for (int mm = 0; mm < 8; mm++)
            #pragma unroll
            for (int gt = 0; gt < 4; gt++) Gc[mm][gt] = Gn[mm][gt];
        __syncthreads();
    }
}

// ---------------------------------------------------------------------------
// FC1 split-K, bf16 mma, double-buffered (unchanged from R10).
// ---------------------------------------------------------------------------
__global__ void fc1_mma_k()
{
    extern __shared__ uint32_t fsm[];
    uint32_t (*As)[20] = (uint32_t(*)[20])fsm;
    uint32_t (*Bs)[20] = (uint32_t(*)[20])(fsm + 2*256*20);

    const int tid  = threadIdx.x;
    const int lane = tid & 31;
    const int wid  = tid >> 5;
    const int g    = lane >> 2, tq = lane & 3;
    const int wm0  = (wid & 1) * 128;
    const int wn0  = (wid >> 1) * 32;
    const int k0   = blockIdx.x * 512;

    float acc[8][4][4];
    #pragma unroll
    for (int i = 0; i < 8; i++)
        #pragma unroll
        for (int j = 0; j < 4; j++)
            #pragma unroll
            for (int q = 0; q < 4; q++) acc[i][j][q] = 0.f;

    auto prefetch = [&](int b, int kt) {
        #pragma unroll
        for (int i = 0; i < 4; i++) {
            int l = i*256 + tid;
            int m = l >> 2, kq = l & 3;
            cp16(smem_u32(&As[b*256 + m][kq*4]),
                 g_hcat + (size_t)m*65536 + k0 + kt + kq*8);
        }
        #pragma unroll
        for (int i = 0; i < 2; i++) {
            int l = i*256 + tid;
            int n = l >> 2, kq = l & 3;
            cp16(smem_u32(&Bs[b*128 + n][kq*4]),
                 g_fc1wb16 + (size_t)n*65536 + k0 + kt + kq*8);
        }
    };

    prefetch(0, 0);
    cp_commit();
    cp_wait0();
    __syncthreads();

    for (int it = 0; it < 16; it++) {
        const int b = it & 1;
        if (it < 15) { prefetch(b^1, (it+1)*32); cp_commit(); }
        #pragma unroll
        for (int k16 = 0; k16 < 2; k16++) {
            const int kp = k16*8;
            uint32_t a[8][4], bb[4][2];
            #pragma unroll
            for (int fi = 0; fi < 8; fi++) {
                int r = b*256 + wm0 + fi*16;
                a[fi][0] = As[r+g  ][kp+tq];
                a[fi][1] = As[r+g+8][kp+tq];
                a[fi][2] = As[r+g  ][kp+tq+4];
                a[fi][3] = As[r+g+8][kp+tq+4];
            }
            #pragma unroll
            for (int fj = 0; fj < 4; fj++) {
                int cn = b*128 + wn0 + fj*8 + g;
                bb[fj][0] = Bs[cn][kp+tq];
                bb[fj][1] = Bs[cn][kp+tq+4];
            }
            #pragma unroll
            for (int fi = 0; fi < 8; fi++)
                #pragma unroll
                for (int fj = 0; fj < 4; fj++)
                    mma_bf16(acc[fi][fj], a[fi], bb[fj]);
        }
        if (it < 15) cp_wait0();
        __syncthreads();
    }

    float* part = g_fc1part + (size_t)blockIdx.x*256*128;
    #pragma unroll
    for (int fj = 0; fj < 4; fj++) {
        int n0 = wn0 + fj*8 + 2*tq;
        #pragma unroll
        for (int fi = 0; fi < 8; fi++) {
            #pragma unroll
            for (int p = 0; p < 2; p++) {
                int m = wm0 + fi*16 + g + p*8;
                *(float2*)(part + (size_t)m*128 + n0) =
                    make_float2(acc[fi][fj][p*2+0], acc[fi][fj][p*2+1]);
            }
        }
    }
}

__global__ void fc1_reduce_k(const float* __restrict__ fc1b)
{
    int idx = blockIdx.x*256 + threadIdx.x;
    int m = idx >> 7, h = idx & 127;
    float s = fc1b[h];
    #pragma unroll 8
    for (int kc = 0; kc < 128; kc++)
        s += g_fc1part[((size_t)kc*256 + m)*128 + h];
    g_z1[(size_t)m*128 + h] = fmaxf(s, 0.f);
}

__global__ void score_k(const float* __restrict__ fsw, const float* __restrict__ fsb,
                        float* __restrict__ out)
{
    __shared__ float w[128];
    __shared__ float fr[256];
    int tid = threadIdx.x;
    if (tid < 128) w[tid] = fsw[tid];
    __syncthreads();
    float acc = fsb[0];
    #pragma unroll 8
    for (int h = 0; h < 128; h++) acc += g_z1[(size_t)tid*128 + h] * w[h];
    float sc = 1.f / (1.f + expf(-acc)) * 4.f + 1.f;
    out[16 + tid] = sc;
    fr[tid] = sc;
    __syncthreads();
    if (tid < 16) {
        float s = 0.f;
        #pragma unroll
        for (int f = 0; f < 16; f++) s += fr[tid*16 + f];
        out[tid] = s * (1.f/16.f);
    }
}

// ---------------------------------------------------------------------------
extern "C" void kernel_launch(void* const* d_in, const int* in_sizes, int n_in,
                              void* d_out, int out_size)
{
    const float *audio,*w0,*b0,*w1,*b1,*w2,*b2,*w3,*b3;
    const float *Wihf,*Whhf,*bihf,*bhhf,*Wihb,*Whhb,*bihb,*bhhb;
    const float *fc1w,*fc1b,*fsw,*fsb;
    if (n_in >= 22 && in_sizes[1] == 144) {
        audio=(const float*)d_in[0];
        w0=(const float*)d_in[1];  b0=(const float*)d_in[2];
        w1=(const float*)d_in[3];  b1=(const float*)d_in[4];
        w2=(const float*)d_in[5];  b2=(const float*)d_in[6];
        w3=(const float*)d_in[7];  b3=(const float*)d_in[8];
        Wihf=(const float*)d_in[9];  Whhf=(const float*)d_in[10];
        bihf=(const float*)d_in[11]; bhhf=(const float*)d_in[12];
        Wihb=(const float*)d_in[13]; Whhb=(const float*)d_in[14];
        bihb=(const float*)d_in[15]; bhhb=(const float*)d_in[16];
        fc1w=(const float*)d_in[17]; fc1b=(const float*)d_in[18];
        fsw=(const float*)d_in[19];  fsb=(const float*)d_in[20];
    } else {
        audio=(const float*)d_in[0];
        w0=(const float*)d_in[2];  b0=(const float*)d_in[3];
        w1=(const float*)d_in[4];  b1=(const float*)d_in[5];
        w2=(const float*)d_in[6];  b2=(const float*)d_in[7];
        w3=(const float*)d_in[8];  b3=(const float*)d_in[9];
        Wihf=(const float*)d_in[10]; Whhf=(const float*)d_in[11];
        bihf=(const float*)d_in[12]; bhhf=(const float*)d_in[13];
        Wihb=(const float*)d_in[14]; Whhb=(const float*)d_in[15];
        bihb=(const float*)d_in[16]; bhhb=(const float*)d_in[17];
        fc1w=(const float*)d_in[18]; fc1b=(const float*)d_in[19];
        fsw=(const float*)d_in[20];  fsb=(const float*)d_in[21];
    }

    __nv_bfloat16 *x0,*x1,*x2,*xT,*wT1,*wT2,*wT3;
    cudaGetSymbolAddress((void**)&x0, g_x0);
    cudaGetSymbolAddress((void**)&x1, g_x1);
    cudaGetSymbolAddress((void**)&x2, g_x2);
    cudaGetSymbolAddress((void**)&xT, g_xT);
    cudaGetSymbolAddress((void**)&wT1, g_wT1);
    cudaGetSymbolAddress((void**)&wT2, g_wT2);
    cudaGetSymbolAddress((void**)&wT3, g_wT3);

    const int sc1 = (130*(27*8 +4) + 9*32 *(8 +4))*4;
    const int sc2 = (130*(9*16 +4) + 9*64 *(16+4))*4;
    const int sc3 = (130*(3*32 +4) + 9*128*(32+4))*4;
    const int sf  = 2*(256 + 128)*20*4;
    cudaFuncSetAttribute(conv_mma_k<16, 32,27,9,false>, cudaFuncAttributeMaxDynamicSharedMemorySize, sc1);
    cudaFuncSetAttribute(conv_mma_k<32, 64, 9,3,false>, cudaFuncAttributeMaxDynamicSharedMemorySize, sc2);
    cudaFuncSetAttribute(conv_mma_k<64,128, 3,1,true >, cudaFuncAttributeMaxDynamicSharedMemorySize, sc3);
    cudaFuncSetAttribute(fc1_mma_k, cudaFuncAttributeMaxDynamicSharedMemorySize, sf);

    wtrans_k<<<(96768 + 255)/256, 256>>>(w1, w2, w3);
    prep_bf16_k<<<8192, 256>>>(Wihf, Wihb, fc1w);

    conv0_k<<<(BF*NT*27)/256, 256>>>(audio, w0, b0, x0);
    conv_mma_k<16, 32,27,9,false><<<dim3(2,BF), 256, sc1>>>(x0, wT1, b1, x1);
    conv_mma_k<32, 64, 9,3,false><<<dim3(2,BF), 256, sc2>>>(x1, wT2, b2, x2);
    conv_mma_k<64,128, 3,1,true ><<<dim3(2,BF), 256, sc3>>>(x2, wT3, b3, xT);

    gemm_xw_k<<<dim3(4,512,2), 256>>>(xT, bihf, bhhf, bihb, bhhb);

    lstm_k<<<dim3(16,2), 256>>>(Whhf, Whhb);

    fc1_mma_k<<<128, 256, sf>>>();
    fc1_reduce_k<<<128, 256>>>(fc1b);
    score_k<<<1, 256>>>(fsw, fsb, (float*)d_out);
}

// round 12
// speedup vs baseline: 1.1968x; 1.1968x over previous
#include <cuda_runtime.h>
#include <cuda_bf16.h>
#include <cstdint>
#include <math.h>

#define BF 256
#define NT 256

// ---------------------------------------------------------------------------
// Static scratch. All intermediates bf16.
// ---------------------------------------------------------------------------
__device__ __align__(16) __nv_bfloat16 g_x0[(size_t)BF*NT*27*16];
__device__ __align__(16) __nv_bfloat16 g_x1[(size_t)BF*NT*9*32];
__device__ __align__(16) __nv_bfloat16 g_x2[(size_t)BF*NT*3*64];
__device__ __align__(16) __nv_bfloat16 g_xT[(size_t)NT*BF*128];
__device__ __align__(16) __nv_bfloat16 g_G[(size_t)2*65536*512];
__device__ __align__(16) __nv_bfloat16 g_hcat[(size_t)BF*65536];
__device__ __align__(16) float g_fc1part[(size_t)128*256*128];
__device__ __align__(16) float g_z1[(size_t)256*128];
__device__ __align__(16) __nv_bfloat16 g_wT1[9*32*16];
__device__ __align__(16) __nv_bfloat16 g_wT2[9*64*32];
__device__ __align__(16) __nv_bfloat16 g_wT3[9*128*64];
__device__ __align__(16) __nv_bfloat16 g_Wihb16[(size_t)2*512*128];
__device__ __align__(16) __nv_bfloat16 g_fc1wb16[(size_t)128*65536];

// ---------------------------------------------------------------------------
// helpers
// ---------------------------------------------------------------------------
__device__ __forceinline__ uint32_t packbf(float lo, float hi)
{
    __nv_bfloat162 h = __floats2bfloat162_rn(lo, hi);
    return *(uint32_t*)&h;
}
__device__ __forceinline__ void mma_bf16(float* d, const uint32_t* a, const uint32_t* b)
{
    asm("mma.sync.aligned.m16n8k16.row.col.f32.bf16.bf16.f32 "
        "{%0,%1,%2,%3}, {%4,%5,%6,%7}, {%8,%9}, {%0,%1,%2,%3};"
        : "+f"(d[0]), "+f"(d[1]), "+f"(d[2]), "+f"(d[3])
        : "r"(a[0]), "r"(a[1]), "r"(a[2]), "r"(a[3]), "r"(b[0]), "r"(b[1]));
}
__device__ __forceinline__ uint32_t smem_u32(const void* p)
{
    return (uint32_t)__cvta_generic_to_shared(p);
}
__device__ __forceinline__ void cp16(uint32_t dst, const void* src)
{
    asm volatile("cp.async.cg.shared.global [%0], [%1], 16;" :: "r"(dst), "l"(src));
}
__device__ __forceinline__ void cp16z(uint32_t dst, const void* src)
{
    asm volatile("cp.async.cg.shared.global [%0], [%1], 16, 0;" :: "r"(dst), "l"(src));
}
__device__ __forceinline__ void cp_commit() { asm volatile("cp.async.commit_group;"); }
__device__ __forceinline__ void cp_wait0()  { asm volatile("cp.async.wait_group 0;"); }
__device__ __forceinline__ void cp_wait1()  { asm volatile("cp.async.wait_group 1;"); }

// ---------------------------------------------------------------------------
// Prep kernels
// ---------------------------------------------------------------------------
__global__ void wtrans_k(const float* __restrict__ w1, const float* __restrict__ w2,
                         const float* __restrict__ w3)
{
    int idx = blockIdx.x*256 + threadIdx.x;
    const float* w; __nv_bfloat16* wT; int CIN, COUT;
    if (idx < 4608)        { w = w1; wT = g_wT1; CIN = 16; COUT = 32; }
    else if (idx < 23040)  { w = w2; wT = g_wT2; CIN = 32; COUT = 64; idx -= 4608; }
    else if (idx < 96768)  { w = w3; wT = g_wT3; CIN = 64; COUT = 128; idx -= 23040; }
    else return;
    int ci  = idx % CIN;
    int r   = idx / CIN;
    int co  = r % COUT;
    int tap = r / COUT;
    wT[idx] = __float2bfloat16(w[(co*CIN + ci)*9 + tap]);
}

__global__ void prep_bf16_k(const float* __restrict__ Wihf, const float* __restrict__ Wihb,
                            const float* __restrict__ fc1w)
{
    const size_t total = 131072 + 8388608;
    for (size_t i = (size_t)blockIdx.x*256 + threadIdx.x; i < total;
         i += (size_t)gridDim.x*256) {
        if (i < 65536)        g_Wihb16[i] = __float2bfloat16(Wihf[i]);
        else if (i < 131072)  g_Wihb16[i] = __float2bfloat16(Wihb[i-65536]);
        else                  g_fc1wb16[i-131072] = __float2bfloat16(fc1w[i-131072]);
    }
}

// ---------------------------------------------------------------------------
// conv0: CIN=1 -> 16, direct. out NHWC bf16 [bf][t][27][16].
// ---------------------------------------------------------------------------
__global__ void conv0_k(const float* __restrict__ audio, const float* __restrict__ w,
                        const float* __restrict__ bias, __nv_bfloat16* __restrict__ out)
{
    __shared__ float wsm[9][16];
    __shared__ float bsm[16];
    int tid = threadIdx.x;
    if (tid < 144) wsm[tid % 9][tid / 9] = w[tid];
    if (tid < 16)  bsm[tid] = bias[tid];
    __syncthreads();

    size_t idx = (size_t)blockIdx.x*256 + tid;
    int wo = (int)(idx % 27);
    size_t r = idx / 27;
    int t  = (int)(r % NT);
    int bf = (int)(r / NT);

    float acc[16];
    #pragma unroll
    for (int co = 0; co < 16; co++) acc[co] = bsm[co];

    #pragma unroll
    for (int kh = 0; kh < 3; kh++) {
        int ti = t + kh - 1;
        if (ti < 0 || ti >= NT) continue;
        #pragma unroll
        for (int kw = 0; kw < 3; kw++) {
            int wc = 3*wo + kw - 1;
            if (wc < 0 || wc >= 81) continue;
            float v = audio[((size_t)bf*NT + ti)*81 + wc];
            #pragma unroll
            for (int co = 0; co < 16; co++) acc[co] += v * wsm[kh*3+kw][co];
        }
    }
    uint32_t* o = (uint32_t*)(out + idx*16);
    #pragma unroll
    for (int q = 0; q < 8; q++)
        o[q] = packbf(fmaxf(acc[q*2+0], 0.f), fmaxf(acc[q*2+1], 0.f));
}

// ---------------------------------------------------------------------------
// Conv, bf16 mma, single tile load per block (unchanged from R10).
// ---------------------------------------------------------------------------
template<int CIN,int COUT,int WIN,int WOUT,bool TOUT>
__global__ void conv_mma_k(const __nv_bfloat16* __restrict__ x,
                           const __nv_bfloat16* __restrict__ wT,
                           const float* __restrict__ bias,
                           __nv_bfloat16* __restrict__ out)
{
    constexpr int CU  = CIN/2;
    constexpr int LDT = WIN*CU + 4;
    constexpr int LDB = CU + 4;
    constexpr int NWN = COUT/32, WMW = 8/NWN, MFR = 128/WMW/16;
    constexpr int NK16 = CIN/16;
    extern __shared__ uint32_t sm[];
    uint32_t* At = sm;
    uint32_t* Bt = sm + 130*LDT;

    const int tid  = threadIdx.x;
    const int lane = tid & 31;
    const int wid  = tid >> 5;
    const int g    = lane >> 2, tq = lane & 3;
    const int wm0  = (wid % WMW) * (128/WMW);
    const int wn0  = (wid / WMW) * 32;
    const int t0   = blockIdx.x * 128;
    const int bf   = blockIdx.y;

    constexpr int ACH = WIN*CU/4;
    for (int l = tid; l < 130*ACH; l += 256) {
        int row = l / ACH, ch = l % ACH;
        int t_in = t0 + row - 1;
        uint32_t dst = smem_u32(At + row*LDT + ch*4);
        const __nv_bfloat16* src = x + ((size_t)bf*NT + (t_in < 0 ? 0 : (t_in >= NT ? NT-1 : t_in)))*WIN*CIN + ch*8;
        if (t_in >= 0 && t_in < NT) cp16(dst, src);
        else                        cp16z(dst, src);
    }
    constexpr int BCH = CU/4;
    for (int l = tid; l < 9*COUT*BCH; l += 256) {
        int r = l / BCH, ch = l % BCH;
        cp16(smem_u32(Bt + r*LDB + ch*4), wT + (size_t)r*CIN + ch*8);
    }
    cp_commit();
    cp_wait0();
    __syncthreads();

    float bv[4][2];
    #pragma unroll
    for (int fj = 0; fj < 4; fj++) {
        int co0 = wn0 + fj*8 + 2*tq;
        bv[fj][0] = bias[co0]; bv[fj][1] = bias[co0+1];
    }

    #pragma unroll 1
    for (int wo = 0; wo < WOUT; wo++) {
        float acc[MFR][4][4];
        #pragma unroll
        for (int i = 0; i < MFR; i++)
            #pragma unroll
            for (int j = 0; j < 4; j++)
                #pragma unroll
                for (int q = 0; q < 4; q++) acc[i][j][q] = 0.f;

        #pragma unroll
        for (int kh = 0; kh < 3; kh++) {
            #pragma unroll
            for (int kw = 0; kw < 3; kw++) {
                const int wc = 3*wo + kw - 1;
                if (wc < 0 || wc >= WIN) continue;
                const uint32_t* Btap = Bt + (size_t)(kh*3+kw)*COUT*LDB;
                #pragma unroll
                for (int k16 = 0; k16 < NK16; k16++) {
                    const int kp = k16*8;
                    const int ac = wc*CU + kp;
                    uint32_t a[MFR][4], b[4][2];
                    #pragma unroll
                    for (int fi = 0; fi < MFR; fi++) {
                        int r = wm0 + fi*16 + g + kh;
                        a[fi][0] = At[(r  )*LDT + ac + tq];
                        a[fi][1] = At[(r+8)*LDT + ac + tq];
                        a[fi][2] = At[(r  )*LDT + ac + tq + 4];
                        a[fi][3] = At[(r+8)*LDT + ac + tq + 4];
                    }
                    #pragma unroll
                    for (int fj = 0; fj < 4; fj++) {
                        int cn = wn0 + fj*8 + g;
                        b[fj][0] = Btap[cn*LDB + kp + tq];
                        b[fj][1] = Btap[cn*LDB + kp + tq + 4];
                    }
                    #pragma unroll
                    for (int fi = 0; fi < MFR; fi++)
                        #pragma unroll
                        for (int fj = 0; fj < 4; fj++)
                            mma_bf16(acc[fi][fj], a[fi], b[fj]);
                }
            }
        }

        #pragma unroll
        for (int fj = 0; fj < 4; fj++) {
            int co0 = wn0 + fj*8 + 2*tq;
            #pragma unroll
            for (int fi = 0; fi < MFR; fi++) {
                #pragma unroll
                for (int p = 0; p < 2; p++) {
                    int m = wm0 + fi*16 + g + p*8;
                    uint32_t v = packbf(fmaxf(acc[fi][fj][p*2+0] + bv[fj][0], 0.f),
                                        fmaxf(acc[fi][fj][p*2+1] + bv[fj][1], 0.f));
                    size_t base;
                    if (TOUT) base = ((size_t)(t0+m)*BF + bf)*COUT + co0;
                    else      base = (((size_t)bf*NT + (t0+m))*WOUT + wo)*COUT + co0;
                    *(uint32_t*)(out + base) = v;
                }
            }
        }
    }
}

// ---------------------------------------------------------------------------
// Input-projection GEMM, bf16 mma. 3-stage cp.async pipeline +
// smem-staged coalesced epilogue.
// ---------------------------------------------------------------------------
__global__ void __launch_bounds__(256)
gemm_xw_k(const __nv_bfloat16* __restrict__ X,
          const float* __restrict__ bihf, const float* __restrict__ bhhf,
          const float* __restrict__ bihb, const float* __restrict__ bhhb)
{
    const int dir = blockIdx.z;
    const __nv_bfloat16* W = g_Wihb16 + (size_t)dir*65536;
    const float* b1 = dir ? bihb : bihf;
    const float* b2 = dir ? bhhb : bhhf;
    __nv_bfloat16* out = g_G + (size_t)dir*65536*512;

    extern __shared__ uint32_t gsm[];
    uint32_t (*As)[20] = (uint32_t(*)[20])gsm;              // [3*128][20]
    uint32_t (*Bs)[20] = (uint32_t(*)[20])(gsm + 3*128*20); // [3*128][20]

    const int tid  = threadIdx.x;
    const int lane = tid & 31;
    const int wid  = tid >> 5;
    const int g    = lane >> 2, tq = lane & 3;
    const int wm0  = (wid & 1) * 64;
    const int wn0  = (wid >> 1) * 32;
    const int m0   = blockIdx.y * 128, n0 = blockIdx.x * 128;

    const int ma = tid >> 2, ka = tid & 3;
    const int mb = (256 + tid) >> 2, kb = (256 + tid) & 3;

    float acc[4][4][4];
    #pragma unroll
    for (int i = 0; i < 4; i++)
        #pragma unroll
        for (int j = 0; j < 4; j++)
            #pragma unroll
            for (int q = 0; q < 4; q++) acc[i][j][q] = 0.f;

    auto prefetch = [&](int s, int kt) {
        cp16(smem_u32(&As[s*128+ma][ka*4]), X + (size_t)(m0+ma)*128 + kt + ka*8);
        cp16(smem_u32(&As[s*128+mb][kb*4]), X + (size_t)(m0+mb)*128 + kt + kb*8);
        cp16(smem_u32(&Bs[s*128+ma][ka*4]), W + (size_t)(n0+ma)*128 + kt + ka*8);
        cp16(smem_u32(&Bs[s*128+mb][kb*4]), W + (size_t)(n0+mb)*128 + kt + kb*8);
        cp_commit();
    };

    prefetch(0, 0);
    prefetch(1, 32);

    for (int it = 0; it < 4; it++) {
        const int s = it % 3;
        if (it < 3) cp_wait1(); else cp_wait0();
        __syncthreads();
        if (it + 2 < 4) prefetch((it+2) % 3, (it+2)*32);

        #pragma unroll
        for (int k16 = 0; k16 < 2; k16++) {
            const int kp = k16*8;
            uint32_t a[4][4], bb[4][2];
            #pragma unroll
            for (int fi = 0; fi < 4; fi++) {
                int r = s*128 + wm0 + fi*16;
                a[fi][0] = As[r+g  ][kp+tq];
                a[fi][1] = As[r+g+8][kp+tq];
                a[fi][2] = As[r+g  ][kp+tq+4];
                a[fi][3] = As[r+g+8][kp+tq+4];
            }
            #pragma unroll
            for (int fj = 0; fj < 4; fj++) {
                int cn = s*128 + wn0 + fj*8 + g;
                bb[fj][0] = Bs[cn][kp+tq];
                bb[fj][1] = Bs[cn][kp+tq+4];
            }
            #pragma unroll
            for (int fi = 0; fi < 4; fi++)
                #pragma unroll
                for (int fj = 0; fj < 4; fj++)
                    mma_bf16(acc[fi][fj], a[fi], bb[fj]);
        }
    }

    // ---- staged epilogue: acc -> smem bf16 tile -> coalesced stores ----
    __syncthreads();
    __nv_bfloat16 (*Ct)[136] = (__nv_bfloat16(*)[136])gsm;
    #pragma unroll
    for (int fj = 0; fj < 4; fj++) {
        int gate0 = n0 + wn0 + fj*8 + 2*tq;
        float bv0 = b1[gate0]   + b2[gate0];
        float bv1 = b1[gate0+1] + b2[gate0+1];
        int ncol = wn0 + fj*8 + 2*tq;
        #pragma unroll
        for (int fi = 0; fi < 4; fi++) {
            #pragma unroll
            for (int p = 0; p < 2; p++) {
                int m = wm0 + fi*16 + g + p*8;
                *(uint32_t*)&Ct[m][ncol] =
                    packbf(acc[fi][fj][p*2+0] + bv0, acc[fi][fj][p*2+1] + bv1);
            }
        }
    }
    __syncthreads();
    #pragma unroll
    for (int i = 0; i < 8; i++) {
        int idx = i*256 + tid;
        int row = idx >> 4, c16 = idx & 15;
        uint4 v = *(uint4*)&Ct[row][c16*8];
        *(uint4*)(out + (size_t)(m0+row)*512 + n0 + c16*8) = v;
    }
}

// ---------------------------------------------------------------------------
// LSTM recurrence, cluster edition (R10, best known).
// ---------------------------------------------------------------------------
__device__ __forceinline__ float sigf(float x) { return 1.f / (1.f + expf(-x)); }

__global__ void __cluster_dims__(2,1,1) __launch_bounds__(256,1)
lstm_k(const float* __restrict__ Whhf, const float* __restrict__ Whhb)
{
    __shared__ __nv_bfloat16 hbuf[2*16*136];
    __shared__ float zsm[16][258];

    const int tid  = threadIdx.x;
    const int lane = tid & 31;
    const int w    = tid >> 5;
    const int g    = lane >> 2, tq = lane & 3;
    const int rank = blockIdx.x & 1;
    const int dir  = blockIdx.z;
    const int nb0  = blockIdx.y * 16;
    const float* Whh = dir ? Whhb : Whhf;
    const __nv_bfloat16* G = g_G + (size_t)dir*65536*512;

    uint32_t wb[4][8][2];
    #pragma unroll
    for (int fj = 0; fj < 4; fj++) {
        int rl = w*32 + fj*8 + g;
        int grow = (rl >> 6)*128 + rank*64 + (rl & 63);
        const float* wr = Whh + (size_t)grow*128;
        #pragma unroll
        for (int kt = 0; kt < 8; kt++) {
            wb[fj][kt][0] = packbf(wr[kt*16 + 2*tq    ], wr[kt*16 + 2*tq + 1]);
            wb[fj][kt][1] = packbf(wr[kt*16 + 2*tq + 8], wr[kt*16 + 2*tq + 9]);
        }
    }

    {
        uint32_t* hz = (uint32_t*)hbuf;
        for (int idx = tid; idx < 2*16*136/2; idx += 256) hz[idx] = 0u;
    }

    uint32_t hbuf_u32;
    { uint64_t tmp;
      asm("cvta.to.shared.u64 %0, %1;" : "=l"(tmp) : "l"((__nv_bfloat16*)hbuf));
      hbuf_u32 = (uint32_t)tmp; }

    asm volatile("barrier.cluster.arrive.aligned;\n\tbarrier.cluster.wait.aligned;" ::: "memory");

    const int j    = tid & 63;
    const int bq   = tid >> 6;
    const int gcol = rank*64 + j;
    const int peer = rank ^ 1;
    float c[4] = {0.f, 0.f, 0.f, 0.f};

    float Gc[4][4], Gn[4][4];
    {
        int t0 = dir ? 255 : 0;
        #pragma unroll
        for (int mm = 0; mm < 4; mm++)
            #pragma unroll
            for (int gt = 0; gt < 4; gt++)
                Gc[mm][gt] = __bfloat162float(G[((size_t)t0*256 + nb0 + bq*4 + mm)*512 + gt*128 + gcol]);
    }

    for (int s = 0; s < 256; s++) {
        const int t   = dir ? (255 - s) : s;
        const int cur = s & 1, nxt = cur ^ 1;

        float acc[4][4];
        #pragma unroll
        for (int fj = 0; fj < 4; fj++)
            #pragma unroll
            for (int q = 0; q < 4; q++) acc[fj][q] = 0.f;

        const uint32_t* hb = (const uint32_t*)(hbuf + cur*16*136);
        #pragma unroll
        for (int kt = 0; kt < 8; kt++) {
            const int kp = kt*8;
            uint32_t a[4];
            a[0] = hb[(g  )*68 + kp + tq];
            a[1] = hb[(g+8)*68 + kp + tq];
            a[2] = hb[(g  )*68 + kp + tq + 4];
            a[3] = hb[(g+8)*68 + kp + tq + 4];
            #pragma unroll
            for (int fj = 0; fj < 4; fj++)
                mma_bf16(acc[fj], a, wb[fj][kt]);
        }
        #pragma unroll
        for (int fj = 0; fj < 4; fj++) {
            int nloc = w*32 + fj*8 + 2*tq;
            *(float2*)&zsm[g  ][nloc] = make_float2(acc[fj][0], acc[fj][1]);
            *(float2*)&zsm[g+8][nloc] = make_float2(acc[fj][2], acc[fj][3]);
        }
        __syncthreads();

        if (s < 255) {
            int tn = dir ? (254 - s) : (s + 1);
            #pragma unroll
            for (int mm = 0; mm < 4; mm++)
                #pragma unroll
                for (int gt = 0; gt < 4; gt++)
                    Gn[mm][gt] = __bfloat162float(G[((size_t)tn*256 + nb0 + bq*4 + mm)*512 + gt*128 + gcol]);
        }

        #pragma unroll
        for (int mm = 0; mm < 4; mm++) {
            int m = bq*4 + mm;
            float ai = zsm[m][0*64 + j] + Gc[mm][0];
            float af = zsm[m][1*64 + j] + Gc[mm][1];
            float ag = zsm[m][2*64 + j] + Gc[mm][2];
            float ao = zsm[m][3*64 + j] + Gc[mm][3];
            float iv = sigf(ai);
            float fv = sigf(af);
            float gv = tanhf(ag);
            float ov = sigf(ao);
            c[mm] = fv*c[mm] + iv*gv;
            float hv = ov * tanhf(c[mm]);
            __nv_bfloat16 hb16 = __float2bfloat16(hv);
            g_hcat[(size_t)(nb0+m)*65536 + t*256 + dir*128 + gcol] = hb16;
            int off = (nxt*16 + m)*136 + gcol;
            hbuf[off] = hb16;
            unsigned short hu = *(unsigned short*)&hb16;
            uint32_t raddr;
            asm volatile("mapa.shared::cluster.u32 %0, %1, %2;"
                         : "=r"(raddr) : "r"(hbuf_u32 + (uint32_t)off*2u), "r"(peer));
            asm volatile("st.shared::cluster.b16 [%0], %1;" :: "r"(raddr), "h"(hu) : "memory");
        }
        #pragma unroll
        for (int mm = 0; mm < 4; mm++)
            #pragma unroll
            for (int gt = 0; gt < 4; gt++) Gc[mm][gt] = Gn[mm][gt];
        asm volatile("barrier.cluster.arrive.aligned;\n\tbarrier.cluster.wait.aligned;" ::: "memory");
    }
}

// ---------------------------------------------------------------------------
// FC1 split-K, bf16 mma, double-buffered (unchanged from R10).
// ---------------------------------------------------------------------------
__global__ void fc1_mma_k()
{
    extern __shared__ uint32_t fsm[];
    uint32_t (*As)[20] = (uint32_t(*)[20])fsm;
    uint32_t (*Bs)[20] = (uint32_t(*)[20])(fsm + 2*256*20);

    const int tid  = threadIdx.x;
    const int lane = tid & 31;
    const int wid  = tid >> 5;
    const int g    = lane >> 2, tq = lane & 3;
    const int wm0  = (wid & 1) * 128;
    const int wn0  = (wid >> 1) * 32;
    const int k0   = blockIdx.x * 512;

    float acc[8][4][4];
    #pragma unroll
    for (int i = 0; i < 8; i++)
        #pragma unroll
        for (int j = 0; j < 4; j++)
            #pragma unroll
            for (int q = 0; q < 4; q++) acc[i][j][q] = 0.f;

    auto prefetch = [&](int b, int kt) {
        #pragma unroll
        for (int i = 0; i < 4; i++) {
            int l = i*256 + tid;
            int m = l >> 2, kq = l & 3;
            cp16(smem_u32(&As[b*256 + m][kq*4]),
                 g_hcat + (size_t)m*65536 + k0 + kt + kq*8);
        }
        #pragma unroll
        for (int i = 0; i < 2; i++) {
            int l = i*256 + tid;
            int n = l >> 2, kq = l & 3;
            cp16(smem_u32(&Bs[b*128 + n][kq*4]),
                 g_fc1wb16 + (size_t)n*65536 + k0 + kt + kq*8);
        }
    };

    prefetch(0, 0);
    cp_commit();
    cp_wait0();
    __syncthreads();

    for (int it = 0; it < 16; it++) {
        const int b = it & 1;
        if (it < 15) { prefetch(b^1, (it+1)*32); cp_commit(); }
        #pragma unroll
        for (int k16 = 0; k16 < 2; k16++) {
            const int kp = k16*8;
            uint32_t a[8][4], bb[4][2];
            #pragma unroll
            for (int fi = 0; fi < 8; fi++) {
                int r = b*256 + wm0 + fi*16;
                a[fi][0] = As[r+g  ][kp+tq];
                a[fi][1] = As[r+g+8][kp+tq];
                a[fi][2] = As[r+g  ][kp+tq+4];
                a[fi][3] = As[r+g+8][kp+tq+4];
            }
            #pragma unroll
            for (int fj = 0; fj < 4; fj++) {
                int cn = b*128 + wn0 + fj*8 + g;
                bb[fj][0] = Bs[cn][kp+tq];
                bb[fj][1] = Bs[cn][kp+tq+4];
            }
            #pragma unroll
            for (int fi = 0; fi < 8; fi++)
                #pragma unroll
                for (int fj = 0; fj < 4; fj++)
                    mma_bf16(acc[fi][fj], a[fi], bb[fj]);
        }
        if (it < 15) cp_wait0();
        __syncthreads();
    }

    float* part = g_fc1part + (size_t)blockIdx.x*256*128;
    #pragma unroll
    for (int fj = 0; fj < 4; fj++) {
        int n0 = wn0 + fj*8 + 2*tq;
        #pragma unroll
        for (int fi = 0; fi < 8; fi++) {
            #pragma unroll
            for (int p = 0; p < 2; p++) {
                int m = wm0 + fi*16 + g + p*8;
                *(float2*)(part + (size_t)m*128 + n0) =
                    make_float2(acc[fi][fj][p*2+0], acc[fi][fj][p*2+1]);
            }
        }
    }
}

__global__ void fc1_reduce_k(const float* __restrict__ fc1b)
{
    int idx = blockIdx.x*256 + threadIdx.x;
    int m = idx >> 7, h = idx & 127;
    float s = fc1b[h];
    #pragma unroll 8
    for (int kc = 0; kc < 128; kc++)
        s += g_fc1part[((size_t)kc*256 + m)*128 + h];
    g_z1[(size_t)m*128 + h] = fmaxf(s, 0.f);
}

__global__ void score_k(const float* __restrict__ fsw, const float* __restrict__ fsb,
                        float* __restrict__ out)
{
    __shared__ float w[128];
    __shared__ float fr[256];
    int tid = threadIdx.x;
    if (tid < 128) w[tid] = fsw[tid];
    __syncthreads();
    float acc = fsb[0];
    #pragma unroll 8
    for (int h = 0; h < 128; h++) acc += g_z1[(size_t)tid*128 + h] * w[h];
    float sc = 1.f / (1.f + expf(-acc)) * 4.f + 1.f;
    out[16 + tid] = sc;
    fr[tid] = sc;
    __syncthreads();
    if (tid < 16) {
        float s = 0.f;
        #pragma unroll
        for (int f = 0; f < 16; f++) s += fr[tid*16 + f];
        out[tid] = s * (1.f/16.f);
    }
}

// ---------------------------------------------------------------------------
extern "C" void kernel_launch(void* const* d_in, const int* in_sizes, int n_in,
                              void* d_out, int out_size)
{
    const float *audio,*w0,*b0,*w1,*b1,*w2,*b2,*w3,*b3;
    const float *Wihf,*Whhf,*bihf,*bhhf,*Wihb,*Whhb,*bihb,*bhhb;
    const float *fc1w,*fc1b,*fsw,*fsb;
    if (n_in >= 22 && in_sizes[1] == 144) {
        audio=(const float*)d_in[0];
        w0=(const float*)d_in[1];  b0=(const float*)d_in[2];
        w1=(const float*)d_in[3];  b1=(const float*)d_in[4];
        w2=(const float*)d_in[5];  b2=(const float*)d_in[6];
        w3=(const float*)d_in[7];  b3=(const float*)d_in[8];
        Wihf=(const float*)d_in[9];  Whhf=(const float*)d_in[10];
        bihf=(const float*)d_in[11]; bhhf=(const float*)d_in[12];
        Wihb=(const float*)d_in[13]; Whhb=(const float*)d_in[14];
        bihb=(const float*)d_in[15]; bhhb=(const float*)d_in[16];
        fc1w=(const float*)d_in[17]; fc1b=(const float*)d_in[18];
        fsw=(const float*)d_in[19];  fsb=(const float*)d_in[20];
    } else {
        audio=(const float*)d_in[0];
        w0=(const float*)d_in[2];  b0=(const float*)d_in[3];
        w1=(const float*)d_in[4];  b1=(const float*)d_in[5];
        w2=(const float*)d_in[6];  b2=(const float*)d_in[7];
        w3=(const float*)d_in[8];  b3=(const float*)d_in[9];
        Wihf=(const float*)d_in[10]; Whhf=(const float*)d_in[11];
        bihf=(const float*)d_in[12]; bhhf=(const float*)d_in[13];
        Wihb=(const float*)d_in[14]; Whhb=(const float*)d_in[15];
        bihb=(const float*)d_in[16]; bhhb=(const float*)d_in[17];
        fc1w=(const float*)d_in[18]; fc1b=(const float*)d_in[19];
        fsw=(const float*)d_in[20];  fsb=(const float*)d_in[21];
    }

    __nv_bfloat16 *x0,*x1,*x2,*xT,*wT1,*wT2,*wT3;
    cudaGetSymbolAddress((void**)&x0, g_x0);
    cudaGetSymbolAddress((void**)&x1, g_x1);
    cudaGetSymbolAddress((void**)&x2, g_x2);
    cudaGetSymbolAddress((void**)&xT, g_xT);
    cudaGetSymbolAddress((void**)&wT1, g_wT1);
    cudaGetSymbolAddress((void**)&wT2, g_wT2);
    cudaGetSymbolAddress((void**)&wT3, g_wT3);

    const int sc1 = (130*(27*8 +4) + 9*32 *(8 +4))*4;
    const int sc2 = (130*(9*16 +4) + 9*64 *(16+4))*4;
    const int sc3 = (130*(3*32 +4) + 9*128*(32+4))*4;
    const int sf  = 2*(256 + 128)*20*4;
    const int sg  = 3*2*128*20*4;                 // 61,440 (also covers Ct staging)
    cudaFuncSetAttribute(conv_mma_k<16, 32,27,9,false>, cudaFuncAttributeMaxDynamicSharedMemorySize, sc1);
    cudaFuncSetAttribute(conv_mma_k<32, 64, 9,3,false>, cudaFuncAttributeMaxDynamicSharedMemorySize, sc2);
    cudaFuncSetAttribute(conv_mma_k<64,128, 3,1,true >, cudaFuncAttributeMaxDynamicSharedMemorySize, sc3);
    cudaFuncSetAttribute(fc1_mma_k, cudaFuncAttributeMaxDynamicSharedMemorySize, sf);
    cudaFuncSetAttribute(gemm_xw_k, cudaFuncAttributeMaxDynamicSharedMemorySize, sg);

    wtrans_k<<<(96768 + 255)/256, 256>>>(w1, w2, w3);
    prep_bf16_k<<<8192, 256>>>(Wihf, Wihb, fc1w);

    conv0_k<<<(BF*NT*27)/256, 256>>>(audio, w0, b0, x0);
    conv_mma_k<16, 32,27,9,false><<<dim3(2,BF), 256, sc1>>>(x0, wT1, b1, x1);
    conv_mma_k<32, 64, 9,3,false><<<dim3(2,BF), 256, sc2>>>(x1, wT2, b2, x2);
    conv_mma_k<64,128, 3,1,true ><<<dim3(2,BF), 256, sc3>>>(x2, wT3, b3, xT);

    gemm_xw_k<<<dim3(4,512,2), 256, sg>>>(xT, bihf, bhhf, bihb, bhhb);

    lstm_k<<<dim3(2,16,2), 256>>>(Whhf, Whhb);

    fc1_mma_k<<<128, 256, sf>>>();
    fc1_reduce_k<<<128, 256>>>(fc1b);
    score_k<<<1, 256>>>(fsw, fsb, (float*)d_out);
}

// round 13
// speedup vs baseline: 1.3879x; 1.1597x over previous
#include <cuda_runtime.h>
#include <cuda_bf16.h>
#include <cstdint>
#include <math.h>

#define BF 256
#define NT 256

// ---------------------------------------------------------------------------
// Static scratch. All intermediates bf16.
// ---------------------------------------------------------------------------
__device__ __align__(16) __nv_bfloat16 g_x0[(size_t)BF*NT*27*16];
__device__ __align__(16) __nv_bfloat16 g_x1[(size_t)BF*NT*9*32];
__device__ __align__(16) __nv_bfloat16 g_x2[(size_t)BF*NT*3*64];
__device__ __align__(16) __nv_bfloat16 g_xT[(size_t)NT*BF*128];
__device__ __align__(16) __nv_bfloat16 g_G[(size_t)2*65536*512];
__device__ __align__(16) __nv_bfloat16 g_hcat[(size_t)BF*65536];
__device__ __align__(16) float g_fc1part[(size_t)128*256*128];
__device__ __align__(16) float g_z1[(size_t)256*128];
__device__ __align__(16) __nv_bfloat16 g_wT1[9*32*16];
__device__ __align__(16) __nv_bfloat16 g_wT2[9*64*32];
__device__ __align__(16) __nv_bfloat16 g_wT3[9*128*64];
__device__ __align__(16) __nv_bfloat16 g_Wihb16[(size_t)2*512*128];
__device__ __align__(16) __nv_bfloat16 g_fc1wb16[(size_t)128*65536];

// ---------------------------------------------------------------------------
// helpers
// ---------------------------------------------------------------------------
__device__ __forceinline__ uint32_t packbf(float lo, float hi)
{
    __nv_bfloat162 h = __floats2bfloat162_rn(lo, hi);
    return *(uint32_t*)&h;
}
__device__ __forceinline__ void mma_bf16(float* d, const uint32_t* a, const uint32_t* b)
{
    asm("mma.sync.aligned.m16n8k16.row.col.f32.bf16.bf16.f32 "
        "{%0,%1,%2,%3}, {%4,%5,%6,%7}, {%8,%9}, {%0,%1,%2,%3};"
        : "+f"(d[0]), "+f"(d[1]), "+f"(d[2]), "+f"(d[3])
        : "r"(a[0]), "r"(a[1]), "r"(a[2]), "r"(a[3]), "r"(b[0]), "r"(b[1]));
}
__device__ __forceinline__ uint32_t smem_u32(const void* p)
{
    return (uint32_t)__cvta_generic_to_shared(p);
}
__device__ __forceinline__ void cp16(uint32_t dst, const void* src)
{
    asm volatile("cp.async.cg.shared.global [%0], [%1], 16;" :: "r"(dst), "l"(src));
}
__device__ __forceinline__ void cp16z(uint32_t dst, const void* src)
{
    asm volatile("cp.async.cg.shared.global [%0], [%1], 16, 0;" :: "r"(dst), "l"(src));
}
__device__ __forceinline__ void cp_commit() { asm volatile("cp.async.commit_group;"); }
__device__ __forceinline__ void cp_wait0()  { asm volatile("cp.async.wait_group 0;"); }
__device__ __forceinline__ void cp_wait1()  { asm volatile("cp.async.wait_group 1;"); }

__device__ __forceinline__ float tanh_fast(float x)
{
    float r;
    asm("tanh.approx.f32 %0, %1;" : "=f"(r) : "f"(x));
    return r;
}
__device__ __forceinline__ float sig_fast(float x)
{
    return fmaf(tanh_fast(0.5f*x), 0.5f, 0.5f);
}

// ---------------------------------------------------------------------------
// Prep kernels
// ---------------------------------------------------------------------------
__global__ void wtrans_k(const float* __restrict__ w1, const float* __restrict__ w2,
                         const float* __restrict__ w3)
{
    int idx = blockIdx.x*256 + threadIdx.x;
    const float* w; __nv_bfloat16* wT; int CIN, COUT;
    if (idx < 4608)        { w = w1; wT = g_wT1; CIN = 16; COUT = 32; }
    else if (idx < 23040)  { w = w2; wT = g_wT2; CIN = 32; COUT = 64; idx -= 4608; }
    else if (idx < 96768)  { w = w3; wT = g_wT3; CIN = 64; COUT = 128; idx -= 23040; }
    else return;
    int ci  = idx % CIN;
    int r   = idx / CIN;
    int co  = r % COUT;
    int tap = r / COUT;
    wT[idx] = __float2bfloat16(w[(co*CIN + ci)*9 + tap]);
}

__global__ void prep_bf16_k(const float* __restrict__ Wihf, const float* __restrict__ Wihb,
                            const float* __restrict__ fc1w)
{
    const size_t total = 131072 + 8388608;
    for (size_t i = (size_t)blockIdx.x*256 + threadIdx.x; i < total;
         i += (size_t)gridDim.x*256) {
        if (i < 65536)        g_Wihb16[i] = __float2bfloat16(Wihf[i]);
        else if (i < 131072)  g_Wihb16[i] = __float2bfloat16(Wihb[i-65536]);
        else                  g_fc1wb16[i-131072] = __float2bfloat16(fc1w[i-131072]);
    }
}

// ---------------------------------------------------------------------------
// conv0: CIN=1 -> 16, direct. out NHWC bf16 [bf][t][27][16].
// ---------------------------------------------------------------------------
__global__ void conv0_k(const float* __restrict__ audio, const float* __restrict__ w,
                        const float* __restrict__ bias, __nv_bfloat16* __restrict__ out)
{
    __shared__ float wsm[9][16];
    __shared__ float bsm[16];
    int tid = threadIdx.x;
    if (tid < 144) wsm[tid % 9][tid / 9] = w[tid];
    if (tid < 16)  bsm[tid] = bias[tid];
    __syncthreads();

    size_t idx = (size_t)blockIdx.x*256 + tid;
    int wo = (int)(idx % 27);
    size_t r = idx / 27;
    int t  = (int)(r % NT);
    int bf = (int)(r / NT);

    float acc[16];
    #pragma unroll
    for (int co = 0; co < 16; co++) acc[co] = bsm[co];

    #pragma unroll
    for (int kh = 0; kh < 3; kh++) {
        int ti = t + kh - 1;
        if (ti < 0 || ti >= NT) continue;
        #pragma unroll
        for (int kw = 0; kw < 3; kw++) {
            int wc = 3*wo + kw - 1;
            if (wc < 0 || wc >= 81) continue;
            float v = audio[((size_t)bf*NT + ti)*81 + wc];
            #pragma unroll
            for (int co = 0; co < 16; co++) acc[co] += v * wsm[kh*3+kw][co];
        }
    }
    uint32_t* o = (uint32_t*)(out + idx*16);
    #pragma unroll
    for (int q = 0; q < 8; q++)
        o[q] = packbf(fmaxf(acc[q*2+0], 0.f), fmaxf(acc[q*2+1], 0.f));
}

// ---------------------------------------------------------------------------
// Conv, bf16 mma, single tile load per block (unchanged from R10).
// ---------------------------------------------------------------------------
template<int CIN,int COUT,int WIN,int WOUT,bool TOUT>
__global__ void conv_mma_k(const __nv_bfloat16* __restrict__ x,
                           const __nv_bfloat16* __restrict__ wT,
                           const float* __restrict__ bias,
                           __nv_bfloat16* __restrict__ out)
{
    constexpr int CU  = CIN/2;
    constexpr int LDT = WIN*CU + 4;
    constexpr int LDB = CU + 4;
    constexpr int NWN = COUT/32, WMW = 8/NWN, MFR = 128/WMW/16;
    constexpr int NK16 = CIN/16;
    extern __shared__ uint32_t sm[];
    uint32_t* At = sm;
    uint32_t* Bt = sm + 130*LDT;

    const int tid  = threadIdx.x;
    const int lane = tid & 31;
    const int wid  = tid >> 5;
    const int g    = lane >> 2, tq = lane & 3;
    const int wm0  = (wid % WMW) * (128/WMW);
    const int wn0  = (wid / WMW) * 32;
    const int t0   = blockIdx.x * 128;
    const int bf   = blockIdx.y;

    constexpr int ACH = WIN*CU/4;
    for (int l = tid; l < 130*ACH; l += 256) {
        int row = l / ACH, ch = l % ACH;
        int t_in = t0 + row - 1;
        uint32_t dst = smem_u32(At + row*LDT + ch*4);
        const __nv_bfloat16* src = x + ((size_t)bf*NT + (t_in < 0 ? 0 : (t_in >= NT ? NT-1 : t_in)))*WIN*CIN + ch*8;
        if (t_in >= 0 && t_in < NT) cp16(dst, src);
        else                        cp16z(dst, src);
    }
    constexpr int BCH = CU/4;
    for (int l = tid; l < 9*COUT*BCH; l += 256) {
        int r = l / BCH, ch = l % BCH;
        cp16(smem_u32(Bt + r*LDB + ch*4), wT + (size_t)r*CIN + ch*8);
    }
    cp_commit();
    cp_wait0();
    __syncthreads();

    float bv[4][2];
    #pragma unroll
    for (int fj = 0; fj < 4; fj++) {
        int co0 = wn0 + fj*8 + 2*tq;
        bv[fj][0] = bias[co0]; bv[fj][1] = bias[co0+1];
    }

    #pragma unroll 1
    for (int wo = 0; wo < WOUT; wo++) {
        float acc[MFR][4][4];
        #pragma unroll
        for (int i = 0; i < MFR; i++)
            #pragma unroll
            for (int j = 0; j < 4; j++)
                #pragma unroll
                for (int q = 0; q < 4; q++) acc[i][j][q] = 0.f;

        #pragma unroll
        for (int kh = 0; kh < 3; kh++) {
            #pragma unroll
            for (int kw = 0; kw < 3; kw++) {
                const int wc = 3*wo + kw - 1;
                if (wc < 0 || wc >= WIN) continue;
                const uint32_t* Btap = Bt + (size_t)(kh*3+kw)*COUT*LDB;
                #pragma unroll
                for (int k16 = 0; k16 < NK16; k16++) {
                    const int kp = k16*8;
                    const int ac = wc*CU + kp;
                    uint32_t a[MFR][4], b[4][2];
                    #pragma unroll
                    for (int fi = 0; fi < MFR; fi++) {
                        int r = wm0 + fi*16 + g + kh;
                        a[fi][0] = At[(r  )*LDT + ac + tq];
                        a[fi][1] = At[(r+8)*LDT + ac + tq];
                        a[fi][2] = At[(r  )*LDT + ac + tq + 4];
                        a[fi][3] = At[(r+8)*LDT + ac + tq + 4];
                    }
                    #pragma unroll
                    for (int fj = 0; fj < 4; fj++) {
                        int cn = wn0 + fj*8 + g;
                        b[fj][0] = Btap[cn*LDB + kp + tq];
                        b[fj][1] = Btap[cn*LDB + kp + tq + 4];
                    }
                    #pragma unroll
                    for (int fi = 0; fi < MFR; fi++)
                        #pragma unroll
                        for (int fj = 0; fj < 4; fj++)
                            mma_bf16(acc[fi][fj], a[fi], b[fj]);
                }
            }
        }

        #pragma unroll
        for (int fj = 0; fj < 4; fj++) {
            int co0 = wn0 + fj*8 + 2*tq;
            #pragma unroll
            for (int fi = 0; fi < MFR; fi++) {
                #pragma unroll
                for (int p = 0; p < 2; p++) {
                    int m = wm0 + fi*16 + g + p*8;
                    uint32_t v = packbf(fmaxf(acc[fi][fj][p*2+0] + bv[fj][0], 0.f),
                                        fmaxf(acc[fi][fj][p*2+1] + bv[fj][1], 0.f));
                    size_t base;
                    if (TOUT) base = ((size_t)(t0+m)*BF + bf)*COUT + co0;
                    else      base = (((size_t)bf*NT + (t0+m))*WOUT + wo)*COUT + co0;
                    *(uint32_t*)(out + base) = v;
                }
            }
        }
    }
}

// ---------------------------------------------------------------------------
// Input-projection GEMM (unchanged from R12).
// ---------------------------------------------------------------------------
__global__ void __launch_bounds__(256)
gemm_xw_k(const __nv_bfloat16* __restrict__ X,
          const float* __restrict__ bihf, const float* __restrict__ bhhf,
          const float* __restrict__ bihb, const float* __restrict__ bhhb)
{
    const int dir = blockIdx.z;
    const __nv_bfloat16* W = g_Wihb16 + (size_t)dir*65536;
    const float* b1 = dir ? bihb : bihf;
    const float* b2 = dir ? bhhb : bhhf;
    __nv_bfloat16* out = g_G + (size_t)dir*65536*512;

    extern __shared__ uint32_t gsm[];
    uint32_t (*As)[20] = (uint32_t(*)[20])gsm;
    uint32_t (*Bs)[20] = (uint32_t(*)[20])(gsm + 3*128*20);

    const int tid  = threadIdx.x;
    const int lane = tid & 31;
    const int wid  = tid >> 5;
    const int g    = lane >> 2, tq = lane & 3;
    const int wm0  = (wid & 1) * 64;
    const int wn0  = (wid >> 1) * 32;
    const int m0   = blockIdx.y * 128, n0 = blockIdx.x * 128;

    const int ma = tid >> 2, ka = tid & 3;
    const int mb = (256 + tid) >> 2, kb = (256 + tid) & 3;

    float acc[4][4][4];
    #pragma unroll
    for (int i = 0; i < 4; i++)
        #pragma unroll
        for (int j = 0; j < 4; j++)
            #pragma unroll
            for (int q = 0; q < 4; q++) acc[i][j][q] = 0.f;

    auto prefetch = [&](int s, int kt) {
        cp16(smem_u32(&As[s*128+ma][ka*4]), X + (size_t)(m0+ma)*128 + kt + ka*8);
        cp16(smem_u32(&As[s*128+mb][kb*4]), X + (size_t)(m0+mb)*128 + kt + kb*8);
        cp16(smem_u32(&Bs[s*128+ma][ka*4]), W + (size_t)(n0+ma)*128 + kt + ka*8);
        cp16(smem_u32(&Bs[s*128+mb][kb*4]), W + (size_t)(n0+mb)*128 + kt + kb*8);
        cp_commit();
    };

    prefetch(0, 0);
    prefetch(1, 32);

    for (int it = 0; it < 4; it++) {
        const int s = it % 3;
        if (it < 3) cp_wait1(); else cp_wait0();
        __syncthreads();
        if (it + 2 < 4) prefetch((it+2) % 3, (it+2)*32);

        #pragma unroll
        for (int k16 = 0; k16 < 2; k16++) {
            const int kp = k16*8;
            uint32_t a[4][4], bb[4][2];
            #pragma unroll
            for (int fi = 0; fi < 4; fi++) {
                int r = s*128 + wm0 + fi*16;
                a[fi][0] = As[r+g  ][kp+tq];
                a[fi][1] = As[r+g+8][kp+tq];
                a[fi][2] = As[r+g  ][kp+tq+4];
                a[fi][3] = As[r+g+8][kp+tq+4];
            }
            #pragma unroll
            for (int fj = 0; fj < 4; fj++) {
                int cn = s*128 + wn0 + fj*8 + g;
                bb[fj][0] = Bs[cn][kp+tq];
                bb[fj][1] = Bs[cn][kp+tq+4];
            }
            #pragma unroll
            for (int fi = 0; fi < 4; fi++)
                #pragma unroll
                for (int fj = 0; fj < 4; fj++)
                    mma_bf16(acc[fi][fj], a[fi], bb[fj]);
        }
    }

    __syncthreads();
    __nv_bfloat16 (*Ct)[136] = (__nv_bfloat16(*)[136])gsm;
    #pragma unroll
    for (int fj = 0; fj < 4; fj++) {
        int gate0 = n0 + wn0 + fj*8 + 2*tq;
        float bv0 = b1[gate0]   + b2[gate0];
        float bv1 = b1[gate0+1] + b2[gate0+1];
        int ncol = wn0 + fj*8 + 2*tq;
        #pragma unroll
        for (int fi = 0; fi < 4; fi++) {
            #pragma unroll
            for (int p = 0; p < 2; p++) {
                int m = wm0 + fi*16 + g + p*8;
                *(uint32_t*)&Ct[m][ncol] =
                    packbf(acc[fi][fj][p*2+0] + bv0, acc[fi][fj][p*2+1] + bv1);
            }
        }
    }
    __syncthreads();
    #pragma unroll
    for (int i = 0; i < 8; i++) {
        int idx = i*256 + tid;
        int row = idx >> 4, c16 = idx & 15;
        uint4 v = *(uint4*)&Ct[row][c16*8];
        *(uint4*)(out + (size_t)(m0+row)*512 + n0 + c16*8) = v;
    }
}

// ---------------------------------------------------------------------------
// LSTM recurrence, cluster edition + HW tanh + mbarrier rendezvous.
// ---------------------------------------------------------------------------
__global__ void __cluster_dims__(2,1,1) __launch_bounds__(256,1)
lstm_k(const float* __restrict__ Whhf, const float* __restrict__ Whhb)
{
    __shared__ __nv_bfloat16 hbuf[2*16*136];
    __shared__ float zsm[16][258];
    __shared__ __align__(8) uint64_t mbar;

    const int tid  = threadIdx.x;
    const int lane = tid & 31;
    const int w    = tid >> 5;
    const int g    = lane >> 2, tq = lane & 3;
    const int rank = blockIdx.x & 1;
    const int dir  = blockIdx.z;
    const int nb0  = blockIdx.y * 16;
    const float* Whh = dir ? Whhb : Whhf;
    const __nv_bfloat16* G = g_G + (size_t)dir*65536*512;

    uint32_t wb[4][8][2];
    #pragma unroll
    for (int fj = 0; fj < 4; fj++) {
        int rl = w*32 + fj*8 + g;
        int grow = (rl >> 6)*128 + rank*64 + (rl & 63);
        const float* wr = Whh + (size_t)grow*128;
        #pragma unroll
        for (int kt = 0; kt < 8; kt++) {
            wb[fj][kt][0] = packbf(wr[kt*16 + 2*tq    ], wr[kt*16 + 2*tq + 1]);
            wb[fj][kt][1] = packbf(wr[kt*16 + 2*tq + 8], wr[kt*16 + 2*tq + 9]);
        }
    }

    {
        uint32_t* hz = (uint32_t*)hbuf;
        for (int idx = tid; idx < 2*16*136/2; idx += 256) hz[idx] = 0u;
    }

    uint32_t hbuf_u32, mbar_u32;
    { uint64_t tmp;
      asm("cvta.to.shared.u64 %0, %1;" : "=l"(tmp) : "l"((__nv_bfloat16*)hbuf));
      hbuf_u32 = (uint32_t)tmp;
      asm("cvta.to.shared.u64 %0, %1;" : "=l"(tmp) : "l"(&mbar));
      mbar_u32 = (uint32_t)tmp; }

    if (tid == 0) {
        asm volatile("mbarrier.init.shared.b64 [%0], %1;" :: "r"(mbar_u32), "r"(512u) : "memory");
    }
    __syncthreads();
    asm volatile("barrier.cluster.arrive.aligned;\n\tbarrier.cluster.wait.aligned;" ::: "memory");

    const int j    = tid & 63;
    const int bq   = tid >> 6;
    const int gcol = rank*64 + j;
    const int peer = rank ^ 1;
    uint32_t mbar_remote;
    asm volatile("mapa.shared::cluster.u32 %0, %1, %2;"
                 : "=r"(mbar_remote) : "r"(mbar_u32), "r"(peer));
    float c[4] = {0.f, 0.f, 0.f, 0.f};

    float Gc[4][4], Gn[4][4];
    {
        int t0 = dir ? 255 : 0;
        #pragma unroll
        for (int mm = 0; mm < 4; mm++)
            #pragma unroll
            for (int gt = 0; gt < 4; gt++)
                Gc[mm][gt] = __bfloat162float(G[((size_t)t0*256 + nb0 + bq*4 + mm)*512 + gt*128 + gcol]);
    }

    for (int s = 0; s < 256; s++) {
        const int t   = dir ? (255 - s) : s;
        const int cur = s & 1, nxt = cur ^ 1;

        float acc[4][4];
        #pragma unroll
        for (int fj = 0; fj < 4; fj++)
            #pragma unroll
            for (int q = 0; q < 4; q++) acc[fj][q] = 0.f;

        const uint32_t* hb = (const uint32_t*)(hbuf + cur*16*136);
        #pragma unroll
        for (int kt = 0; kt < 8; kt++) {
            const int kp = kt*8;
            uint32_t a[4];
            a[0] = hb[(g  )*68 + kp + tq];
            a[1] = hb[(g+8)*68 + kp + tq];
            a[2] = hb[(g  )*68 + kp + tq + 4];
            a[3] = hb[(g+8)*68 + kp + tq + 4];
            #pragma unroll
            for (int fj = 0; fj < 4; fj++)
                mma_bf16(acc[fj], a, wb[fj][kt]);
        }
        #pragma unroll
        for (int fj = 0; fj < 4; fj++) {
            int nloc = w*32 + fj*8 + 2*tq;
            *(float2*)&zsm[g  ][nloc] = make_float2(acc[fj][0], acc[fj][1]);
            *(float2*)&zsm[g+8][nloc] = make_float2(acc[fj][2], acc[fj][3]);
        }
        __syncthreads();

        if (s < 255) {
            int tn = dir ? (254 - s) : (s + 1);
            #pragma unroll
            for (int mm = 0; mm < 4; mm++)
                #pragma unroll
                for (int gt = 0; gt < 4; gt++)
                    Gn[mm][gt] = __bfloat162float(G[((size_t)tn*256 + nb0 + bq*4 + mm)*512 + gt*128 + gcol]);
        }

        #pragma unroll
        for (int mm = 0; mm < 4; mm++) {
            int m = bq*4 + mm;
            float ai = zsm[m][0*64 + j] + Gc[mm][0];
            float af = zsm[m][1*64 + j] + Gc[mm][1];
            float ag = zsm[m][2*64 + j] + Gc[mm][2];
            float ao = zsm[m][3*64 + j] + Gc[mm][3];
            float iv = sig_fast(ai);
            float fv = sig_fast(af);
            float gv = tanh_fast(ag);
            float ov = sig_fast(ao);
            c[mm] = fv*c[mm] + iv*gv;
            float hv = ov * tanh_fast(c[mm]);
            __nv_bfloat16 hb16 = __float2bfloat16(hv);
            g_hcat[(size_t)(nb0+m)*65536 + t*256 + dir*128 + gcol] = hb16;
            int off = (nxt*16 + m)*136 + gcol;
            hbuf[off] = hb16;
            unsigned short hu = *(unsigned short*)&hb16;
            uint32_t raddr;
            asm volatile("mapa.shared::cluster.u32 %0, %1, %2;"
                         : "=r"(raddr) : "r"(hbuf_u32 + (uint32_t)off*2u), "r"(peer));
            asm volatile("st.shared::cluster.b16 [%0], %1;" :: "r"(raddr), "h"(hu) : "memory");
        }
        #pragma unroll
        for (int mm = 0; mm < 4; mm++)
            #pragma unroll
            for (int gt = 0; gt < 4; gt++) Gc[mm][gt] = Gn[mm][gt];

        // rendezvous: arrive local (release) FIRST, then remote, then wait.
        asm volatile("mbarrier.arrive.release.cluster.shared::cta.b64 _, [%0];"
                     :: "r"(mbar_u32) : "memory");
        asm volatile("mbarrier.arrive.release.cluster.shared::cluster.b64 _, [%0];"
                     :: "r"(mbar_remote) : "memory");
        {
            const uint32_t parity = (uint32_t)(s & 1);
            uint32_t done;
            asm volatile(
                "{\n\t.reg .pred p;\n\t"
                "mbarrier.try_wait.parity.acquire.cluster.shared::cta.b64 p, [%1], %2;\n\t"
                "selp.b32 %0, 1, 0, p;\n\t}"
                : "=r"(done) : "r"(mbar_u32), "r"(parity) : "memory");
            if (!done) {
                asm volatile(
                    "{\n\t.reg .pred P1;\n\t"
                    "WL_%=:\n\t"
                    "mbarrier.try_wait.parity.acquire.cluster.shared::cta.b64 P1, [%0], %1, 0x989680;\n\t"
                    "@P1 bra.uni WD_%=;\n\t"
                    "bra.uni WL_%=;\n\t"
                    "WD_%=:\n\t}"
                    :: "r"(mbar_u32), "r"(parity) : "memory");
            }
        }
    }
}

// ---------------------------------------------------------------------------
// FC1 split-K, bf16 mma, double-buffered (unchanged).
// ---------------------------------------------------------------------------
__global__ void fc1_mma_k()
{
    extern __shared__ uint32_t fsm[];
    uint32_t (*As)[20] = (uint32_t(*)[20])fsm;
    uint32_t (*Bs)[20] = (uint32_t(*)[20])(fsm + 2*256*20);

    const int tid  = threadIdx.x;
    const int lane = tid & 31;
    const int wid  = tid >> 5;
    const int g    = lane >> 2, tq = lane & 3;
    const int wm0  = (wid & 1) * 128;
    const int wn0  = (wid >> 1) * 32;
    const int k0   = blockIdx.x * 512;

    float acc[8][4][4];
    #pragma unroll
    for (int i = 0; i < 8; i++)
        #pragma unroll
        for (int j = 0; j < 4; j++)
            #pragma unroll
            for (int q = 0; q < 4; q++) acc[i][j][q] = 0.f;

    auto prefetch = [&](int b, int kt) {
        #pragma unroll
        for (int i = 0; i < 4; i++) {
            int l = i*256 + tid;
            int m = l >> 2, kq = l & 3;
            cp16(smem_u32(&As[b*256 + m][kq*4]),
                 g_hcat + (size_t)m*65536 + k0 + kt + kq*8);
        }
        #pragma unroll
        for (int i = 0; i < 2; i++) {
            int l = i*256 + tid;
            int n = l >> 2, kq = l & 3;
            cp16(smem_u32(&Bs[b*128 + n][kq*4]),
                 g_fc1wb16 + (size_t)n*65536 + k0 + kt + kq*8);
        }
    };

    prefetch(0, 0);
    cp_commit();
    cp_wait0();
    __syncthreads();

    for (int it = 0; it < 16; it++) {
        const int b = it & 1;
        if (it < 15) { prefetch(b^1, (it+1)*32); cp_commit(); }
        #pragma unroll
        for (int k16 = 0; k16 < 2; k16++) {
            const int kp = k16*8;
            uint32_t a[8][4], bb[4][2];
            #pragma unroll
            for (int fi = 0; fi < 8; fi++) {
                int r = b*256 + wm0 + fi*16;
                a[fi][0] = As[r+g  ][kp+tq];
                a[fi][1] = As[r+g+8][kp+tq];
                a[fi][2] = As[r+g  ][kp+tq+4];
                a[fi][3] = As[r+g+8][kp+tq+4];
            }
            #pragma unroll
            for (int fj = 0; fj < 4; fj++) {
                int cn = b*128 + wn0 + fj*8 + g;
                bb[fj][0] = Bs[cn][kp+tq];
                bb[fj][1] = Bs[cn][kp+tq+4];
            }
            #pragma unroll
            for (int fi = 0; fi < 8; fi++)
                #pragma unroll
                for (int fj = 0; fj < 4; fj++)
                    mma_bf16(acc[fi][fj], a[fi], bb[fj]);
        }
        if (it < 15) cp_wait0();
        __syncthreads();
    }

    float* part = g_fc1part + (size_t)blockIdx.x*256*128;
    #pragma unroll
    for (int fj = 0; fj < 4; fj++) {
        int n0 = wn0 + fj*8 + 2*tq;
        #pragma unroll
        for (int fi = 0; fi < 8; fi++) {
            #pragma unroll
            for (int p = 0; p < 2; p++) {
                int m = wm0 + fi*16 + g + p*8;
                *(float2*)(part + (size_t)m*128 + n0) =
                    make_float2(acc[fi][fj][p*2+0], acc[fi][fj][p*2+1]);
            }
        }
    }
}

__global__ void fc1_reduce_k(const float* __restrict__ fc1b)
{
    int idx = blockIdx.x*256 + threadIdx.x;
    int m = idx >> 7, h = idx & 127;
    float s = fc1b[h];
    #pragma unroll 8
    for (int kc = 0; kc < 128; kc++)
        s += g_fc1part[((size_t)kc*256 + m)*128 + h];
    g_z1[(size_t)m*128 + h] = fmaxf(s, 0.f);
}

__global__ void score_k(const float* __restrict__ fsw, const float* __restrict__ fsb,
                        float* __restrict__ out)
{
    __shared__ float w[128];
    __shared__ float fr[256];
    int tid = threadIdx.x;
    if (tid < 128) w[tid] = fsw[tid];
    __syncthreads();
    float acc = fsb[0];
    #pragma unroll 8
    for (int h = 0; h < 128; h++) acc += g_z1[(size_t)tid*128 + h] * w[h];
    float sc = 1.f / (1.f + expf(-acc)) * 4.f + 1.f;
    out[16 + tid] = sc;
    fr[tid] = sc;
    __syncthreads();
    if (tid < 16) {
        float s = 0.f;
        #pragma unroll
        for (int f = 0; f < 16; f++) s += fr[tid*16 + f];
        out[tid] = s * (1.f/16.f);
    }
}

// ---------------------------------------------------------------------------
extern "C" void kernel_launch(void* const* d_in, const int* in_sizes, int n_in,
                              void* d_out, int out_size)
{
    const float *audio,*w0,*b0,*w1,*b1,*w2,*b2,*w3,*b3;
    const float *Wihf,*Whhf,*bihf,*bhhf,*Wihb,*Whhb,*bihb,*bhhb;
    const float *fc1w,*fc1b,*fsw,*fsb;
    if (n_in >= 22 && in_sizes[1] == 144) {
        audio=(const float*)d_in[0];
        w0=(const float*)d_in[1];  b0=(const float*)d_in[2];
        w1=(const float*)d_in[3];  b1=(const float*)d_in[4];
        w2=(const float*)d_in[5];  b2=(const float*)d_in[6];
        w3=(const float*)d_in[7];  b3=(const float*)d_in[8];
        Wihf=(const float*)d_in[9];  Whhf=(const float*)d_in[10];
        bihf=(const float*)d_in[11]; bhhf=(const float*)d_in[12];
        Wihb=(const float*)d_in[13]; Whhb=(const float*)d_in[14];
        bihb=(const float*)d_in[15]; bhhb=(const float*)d_in[16];
        fc1w=(const float*)d_in[17]; fc1b=(const float*)d_in[18];
        fsw=(const float*)d_in[19];  fsb=(const float*)d_in[20];
    } else {
        audio=(const float*)d_in[0];
        w0=(const float*)d_in[2];  b0=(const float*)d_in[3];
        w1=(const float*)d_in[4];  b1=(const float*)d_in[5];
        w2=(const float*)d_in[6];  b2=(const float*)d_in[7];
        w3=(const float*)d_in[8];  b3=(const float*)d_in[9];
        Wihf=(const float*)d_in[10]; Whhf=(const float*)d_in[11];
        bihf=(const float*)d_in[12]; bhhf=(const float*)d_in[13];
        Wihb=(const float*)d_in[14]; Whhb=(const float*)d_in[15];
        bihb=(const float*)d_in[16]; bhhb=(const float*)d_in[17];
        fc1w=(const float*)d_in[18]; fc1b=(const float*)d_in[19];
        fsw=(const float*)d_in[20];  fsb=(const float*)d_in[21];
    }

    __nv_bfloat16 *x0,*x1,*x2,*xT,*wT1,*wT2,*wT3;
    cudaGetSymbolAddress((void**)&x0, g_x0);
    cudaGetSymbolAddress((void**)&x1, g_x1);
    cudaGetSymbolAddress((void**)&x2, g_x2);
    cudaGetSymbolAddress((void**)&xT, g_xT);
    cudaGetSymbolAddress((void**)&wT1, g_wT1);
    cudaGetSymbolAddress((void**)&wT2, g_wT2);
    cudaGetSymbolAddress((void**)&wT3, g_wT3);

    const int sc1 = (130*(27*8 +4) + 9*32 *(8 +4))*4;
    const int sc2 = (130*(9*16 +4) + 9*64 *(16+4))*4;
    const int sc3 = (130*(3*32 +4) + 9*128*(32+4))*4;
    const int sf  = 2*(256 + 128)*20*4;
    const int sg  = 3*2*128*20*4;
    cudaFuncSetAttribute(conv_mma_k<16, 32,27,9,false>, cudaFuncAttributeMaxDynamicSharedMemorySize, sc1);
    cudaFuncSetAttribute(conv_mma_k<32, 64, 9,3,false>, cudaFuncAttributeMaxDynamicSharedMemorySize, sc2);
    cudaFuncSetAttribute(conv_mma_k<64,128, 3,1,true >, cudaFuncAttributeMaxDynamicSharedMemorySize, sc3);
    cudaFuncSetAttribute(fc1_mma_k, cudaFuncAttributeMaxDynamicSharedMemorySize, sf);
    cudaFuncSetAttribute(gemm_xw_k, cudaFuncAttributeMaxDynamicSharedMemorySize, sg);

    wtrans_k<<<(96768 + 255)/256, 256>>>(w1, w2, w3);
    prep_bf16_k<<<8192, 256>>>(Wihf, Wihb, fc1w);

    conv0_k<<<(BF*NT*27)/256, 256>>>(audio, w0, b0, x0);
    conv_mma_k<16, 32,27,9,false><<<dim3(2,BF), 256, sc1>>>(x0, wT1, b1, x1);
    conv_mma_k<32, 64, 9,3,false><<<dim3(2,BF), 256, sc2>>>(x1, wT2, b2, x2);
    conv_mma_k<64,128, 3,1,true ><<<dim3(2,BF), 256, sc3>>>(x2, wT3, b3, xT);

    gemm_xw_k<<<dim3(4,512,2), 256, sg>>>(xT, bihf, bhhf, bihb, bhhb);

    lstm_k<<<dim3(2,16,2), 256>>>(Whhf, Whhb);

    fc1_mma_k<<<128, 256, sf>>>();
    fc1_reduce_k<<<128, 256>>>(fc1b);
    score_k<<<1, 256>>>(fsw, fsb, (float*)d_out);
}

// round 14
// speedup vs baseline: 1.5960x; 1.1499x over previous
#include <cuda_runtime.h>
#include <cuda_bf16.h>
#include <cstdint>
#include <math.h>

#define BF 256
#define NT 256

// ---------------------------------------------------------------------------
// Static scratch. All intermediates bf16.
// ---------------------------------------------------------------------------
__device__ __align__(16) __nv_bfloat16 g_x0[(size_t)BF*NT*27*16];
__device__ __align__(16) __nv_bfloat16 g_x1[(size_t)BF*NT*9*32];
__device__ __align__(16) __nv_bfloat16 g_x2[(size_t)BF*NT*3*64];
__device__ __align__(16) __nv_bfloat16 g_xT[(size_t)NT*BF*128];
__device__ __align__(16) __nv_bfloat16 g_G[(size_t)2*65536*512];
__device__ __align__(16) __nv_bfloat16 g_hcat[(size_t)BF*65536];
__device__ __align__(16) float g_fc1part[(size_t)128*256*128];
__device__ __align__(16) float g_z1[(size_t)256*128];
__device__ __align__(16) __nv_bfloat16 g_wT1[9*32*16];
__device__ __align__(16) __nv_bfloat16 g_wT2[9*64*32];
__device__ __align__(16) __nv_bfloat16 g_wT3[9*128*64];
__device__ __align__(16) __nv_bfloat16 g_Wihb16[(size_t)2*512*128];
__device__ __align__(16) __nv_bfloat16 g_fc1wb16[(size_t)128*65536];

// ---------------------------------------------------------------------------
// helpers
// ---------------------------------------------------------------------------
__device__ __forceinline__ uint32_t packbf(float lo, float hi)
{
    __nv_bfloat162 h = __floats2bfloat162_rn(lo, hi);
    return *(uint32_t*)&h;
}
__device__ __forceinline__ void mma_bf16(float* d, const uint32_t* a, const uint32_t* b)
{
    asm("mma.sync.aligned.m16n8k16.row.col.f32.bf16.bf16.f32 "
        "{%0,%1,%2,%3}, {%4,%5,%6,%7}, {%8,%9}, {%0,%1,%2,%3};"
        : "+f"(d[0]), "+f"(d[1]), "+f"(d[2]), "+f"(d[3])
        : "r"(a[0]), "r"(a[1]), "r"(a[2]), "r"(a[3]), "r"(b[0]), "r"(b[1]));
}
__device__ __forceinline__ uint32_t smem_u32(const void* p)
{
    return (uint32_t)__cvta_generic_to_shared(p);
}
__device__ __forceinline__ void cp16(uint32_t dst, const void* src)
{
    asm volatile("cp.async.cg.shared.global [%0], [%1], 16;" :: "r"(dst), "l"(src));
}
__device__ __forceinline__ void cp16z(uint32_t dst, const void* src)
{
    asm volatile("cp.async.cg.shared.global [%0], [%1], 16, 0;" :: "r"(dst), "l"(src));
}
__device__ __forceinline__ void cp_commit() { asm volatile("cp.async.commit_group;"); }
__device__ __forceinline__ void cp_wait0()  { asm volatile("cp.async.wait_group 0;"); }
__device__ __forceinline__ void cp_wait1()  { asm volatile("cp.async.wait_group 1;"); }

__device__ __forceinline__ float tanh_fast(float x)
{
    float r;
    asm("tanh.approx.f32 %0, %1;" : "=f"(r) : "f"(x));
    return r;
}
__device__ __forceinline__ float sig_fast(float x)
{
    return fmaf(tanh_fast(0.5f*x), 0.5f, 0.5f);
}

// ---------------------------------------------------------------------------
// Prep kernels
// ---------------------------------------------------------------------------
__global__ void wtrans_k(const float* __restrict__ w1, const float* __restrict__ w2,
                         const float* __restrict__ w3)
{
    int idx = blockIdx.x*256 + threadIdx.x;
    const float* w; __nv_bfloat16* wT; int CIN, COUT;
    if (idx < 4608)        { w = w1; wT = g_wT1; CIN = 16; COUT = 32; }
    else if (idx < 23040)  { w = w2; wT = g_wT2; CIN = 32; COUT = 64; idx -= 4608; }
    else if (idx < 96768)  { w = w3; wT = g_wT3; CIN = 64; COUT = 128; idx -= 23040; }
    else return;
    int ci  = idx % CIN;
    int r   = idx / CIN;
    int co  = r % COUT;
    int tap = r / COUT;
    wT[idx] = __float2bfloat16(w[(co*CIN + ci)*9 + tap]);
}

__global__ void prep_bf16_k(const float* __restrict__ Wihf, const float* __restrict__ Wihb,
                            const float* __restrict__ fc1w)
{
    const size_t total = 131072 + 8388608;
    for (size_t i = (size_t)blockIdx.x*256 + threadIdx.x; i < total;
         i += (size_t)gridDim.x*256) {
        if (i < 65536)        g_Wihb16[i] = __float2bfloat16(Wihf[i]);
        else if (i < 131072)  g_Wihb16[i] = __float2bfloat16(Wihb[i-65536]);
        else                  g_fc1wb16[i-131072] = __float2bfloat16(fc1w[i-131072]);
    }
}

// ---------------------------------------------------------------------------
// conv0: CIN=1 -> 16, direct. out NHWC bf16 [bf][t][27][16].
// ---------------------------------------------------------------------------
__global__ void conv0_k(const float* __restrict__ audio, const float* __restrict__ w,
                        const float* __restrict__ bias, __nv_bfloat16* __restrict__ out)
{
    __shared__ float wsm[9][16];
    __shared__ float bsm[16];
    int tid = threadIdx.x;
    if (tid < 144) wsm[tid % 9][tid / 9] = w[tid];
    if (tid < 16)  bsm[tid] = bias[tid];
    __syncthreads();

    size_t idx = (size_t)blockIdx.x*256 + tid;
    int wo = (int)(idx % 27);
    size_t r = idx / 27;
    int t  = (int)(r % NT);
    int bf = (int)(r / NT);

    float acc[16];
    #pragma unroll
    for (int co = 0; co < 16; co++) acc[co] = bsm[co];

    #pragma unroll
    for (int kh = 0; kh < 3; kh++) {
        int ti = t + kh - 1;
        if (ti < 0 || ti >= NT) continue;
        #pragma unroll
        for (int kw = 0; kw < 3; kw++) {
            int wc = 3*wo + kw - 1;
            if (wc < 0 || wc >= 81) continue;
            float v = audio[((size_t)bf*NT + ti)*81 + wc];
            #pragma unroll
            for (int co = 0; co < 16; co++) acc[co] += v * wsm[kh*3+kw][co];
        }
    }
    uint32_t* o = (uint32_t*)(out + idx*16);
    #pragma unroll
    for (int q = 0; q < 8; q++)
        o[q] = packbf(fmaxf(acc[q*2+0], 0.f), fmaxf(acc[q*2+1], 0.f));
}

// ---------------------------------------------------------------------------
// Conv, bf16 mma, single tile load per block (unchanged from R10).
// ---------------------------------------------------------------------------
template<int CIN,int COUT,int WIN,int WOUT,bool TOUT>
__global__ void conv_mma_k(const __nv_bfloat16* __restrict__ x,
                           const __nv_bfloat16* __restrict__ wT,
                           const float* __restrict__ bias,
                           __nv_bfloat16* __restrict__ out)
{
    constexpr int CU  = CIN/2;
    constexpr int LDT = WIN*CU + 4;
    constexpr int LDB = CU + 4;
    constexpr int NWN = COUT/32, WMW = 8/NWN, MFR = 128/WMW/16;
    constexpr int NK16 = CIN/16;
    extern __shared__ uint32_t sm[];
    uint32_t* At = sm;
    uint32_t* Bt = sm + 130*LDT;

    const int tid  = threadIdx.x;
    const int lane = tid & 31;
    const int wid  = tid >> 5;
    const int g    = lane >> 2, tq = lane & 3;
    const int wm0  = (wid % WMW) * (128/WMW);
    const int wn0  = (wid / WMW) * 32;
    const int t0   = blockIdx.x * 128;
    const int bf   = blockIdx.y;

    constexpr int ACH = WIN*CU/4;
    for (int l = tid; l < 130*ACH; l += 256) {
        int row = l / ACH, ch = l % ACH;
        int t_in = t0 + row - 1;
        uint32_t dst = smem_u32(At + row*LDT + ch*4);
        const __nv_bfloat16* src = x + ((size_t)bf*NT + (t_in < 0 ? 0 : (t_in >= NT ? NT-1 : t_in)))*WIN*CIN + ch*8;
        if (t_in >= 0 && t_in < NT) cp16(dst, src);
        else                        cp16z(dst, src);
    }
    constexpr int BCH = CU/4;
    for (int l = tid; l < 9*COUT*BCH; l += 256) {
        int r = l / BCH, ch = l % BCH;
        cp16(smem_u32(Bt + r*LDB + ch*4), wT + (size_t)r*CIN + ch*8);
    }
    cp_commit();
    cp_wait0();
    __syncthreads();

    float bv[4][2];
    #pragma unroll
    for (int fj = 0; fj < 4; fj++) {
        int co0 = wn0 + fj*8 + 2*tq;
        bv[fj][0] = bias[co0]; bv[fj][1] = bias[co0+1];
    }

    #pragma unroll 1
    for (int wo = 0; wo < WOUT; wo++) {
        float acc[MFR][4][4];
        #pragma unroll
        for (int i = 0; i < MFR; i++)
            #pragma unroll
            for (int j = 0; j < 4; j++)
                #pragma unroll
                for (int q = 0; q < 4; q++) acc[i][j][q] = 0.f;

        #pragma unroll
        for (int kh = 0; kh < 3; kh++) {
            #pragma unroll
            for (int kw = 0; kw < 3; kw++) {
                const int wc = 3*wo + kw - 1;
                if (wc < 0 || wc >= WIN) continue;
                const uint32_t* Btap = Bt + (size_t)(kh*3+kw)*COUT*LDB;
                #pragma unroll
                for (int k16 = 0; k16 < NK16; k16++) {
                    const int kp = k16*8;
                    const int ac = wc*CU + kp;
                    uint32_t a[MFR][4], b[4][2];
                    #pragma unroll
                    for (int fi = 0; fi < MFR; fi++) {
                        int r = wm0 + fi*16 + g + kh;
                        a[fi][0] = At[(r  )*LDT + ac + tq];
                        a[fi][1] = At[(r+8)*LDT + ac + tq];
                        a[fi][2] = At[(r  )*LDT + ac + tq + 4];
                        a[fi][3] = At[(r+8)*LDT + ac + tq + 4];
                    }
                    #pragma unroll
                    for (int fj = 0; fj < 4; fj++) {
                        int cn = wn0 + fj*8 + g;
                        b[fj][0] = Btap[cn*LDB + kp + tq];
                        b[fj][1] = Btap[cn*LDB + kp + tq + 4];
                    }
                    #pragma unroll
                    for (int fi = 0; fi < MFR; fi++)
                        #pragma unroll
                        for (int fj = 0; fj < 4; fj++)
                            mma_bf16(acc[fi][fj], a[fi], b[fj]);
                }
            }
        }

        #pragma unroll
        for (int fj = 0; fj < 4; fj++) {
            int co0 = wn0 + fj*8 + 2*tq;
            #pragma unroll
            for (int fi = 0; fi < MFR; fi++) {
                #pragma unroll
                for (int p = 0; p < 2; p++) {
                    int m = wm0 + fi*16 + g + p*8;
                    uint32_t v = packbf(fmaxf(acc[fi][fj][p*2+0] + bv[fj][0], 0.f),
                                        fmaxf(acc[fi][fj][p*2+1] + bv[fj][1], 0.f));
                    size_t base;
                    if (TOUT) base = ((size_t)(t0+m)*BF + bf)*COUT + co0;
                    else      base = (((size_t)bf*NT + (t0+m))*WOUT + wo)*COUT + co0;
                    *(uint32_t*)(out + base) = v;
                }
            }
        }
    }
}

// ---------------------------------------------------------------------------
// Input-projection GEMM (unchanged from R12).
// ---------------------------------------------------------------------------
__global__ void __launch_bounds__(256)
gemm_xw_k(const __nv_bfloat16* __restrict__ X,
          const float* __restrict__ bihf, const float* __restrict__ bhhf,
          const float* __restrict__ bihb, const float* __restrict__ bhhb)
{
    const int dir = blockIdx.z;
    const __nv_bfloat16* W = g_Wihb16 + (size_t)dir*65536;
    const float* b1 = dir ? bihb : bihf;
    const float* b2 = dir ? bhhb : bhhf;
    __nv_bfloat16* out = g_G + (size_t)dir*65536*512;

    extern __shared__ uint32_t gsm[];
    uint32_t (*As)[20] = (uint32_t(*)[20])gsm;
    uint32_t (*Bs)[20] = (uint32_t(*)[20])(gsm + 3*128*20);

    const int tid  = threadIdx.x;
    const int lane = tid & 31;
    const int wid  = tid >> 5;
    const int g    = lane >> 2, tq = lane & 3;
    const int wm0  = (wid & 1) * 64;
    const int wn0  = (wid >> 1) * 32;
    const int m0   = blockIdx.y * 128, n0 = blockIdx.x * 128;

    const int ma = tid >> 2, ka = tid & 3;
    const int mb = (256 + tid) >> 2, kb = (256 + tid) & 3;

    float acc[4][4][4];
    #pragma unroll
    for (int i = 0; i < 4; i++)
        #pragma unroll
        for (int j = 0; j < 4; j++)
            #pragma unroll
            for (int q = 0; q < 4; q++) acc[i][j][q] = 0.f;

    auto prefetch = [&](int s, int kt) {
        cp16(smem_u32(&As[s*128+ma][ka*4]), X + (size_t)(m0+ma)*128 + kt + ka*8);
        cp16(smem_u32(&As[s*128+mb][kb*4]), X + (size_t)(m0+mb)*128 + kt + kb*8);
        cp16(smem_u32(&Bs[s*128+ma][ka*4]), W + (size_t)(n0+ma)*128 + kt + ka*8);
        cp16(smem_u32(&Bs[s*128+mb][kb*4]), W + (size_t)(n0+mb)*128 + kt + kb*8);
        cp_commit();
    };

    prefetch(0, 0);
    prefetch(1, 32);

    for (int it = 0; it < 4; it++) {
        const int s = it % 3;
        if (it < 3) cp_wait1(); else cp_wait0();
        __syncthreads();
        if (it + 2 < 4) prefetch((it+2) % 3, (it+2)*32);

        #pragma unroll
        for (int k16 = 0; k16 < 2; k16++) {
            const int kp = k16*8;
            uint32_t a[4][4], bb[4][2];
            #pragma unroll
            for (int fi = 0; fi < 4; fi++) {
                int r = s*128 + wm0 + fi*16;
                a[fi][0] = As[r+g  ][kp+tq];
                a[fi][1] = As[r+g+8][kp+tq];
                a[fi][2] = As[r+g  ][kp+tq+4];
                a[fi][3] = As[r+g+8][kp+tq+4];
            }
            #pragma unroll
            for (int fj = 0; fj < 4; fj++) {
                int cn = s*128 + wn0 + fj*8 + g;
                bb[fj][0] = Bs[cn][kp+tq];
                bb[fj][1] = Bs[cn][kp+tq+4];
            }
            #pragma unroll
            for (int fi = 0; fi < 4; fi++)
                #pragma unroll
                for (int fj = 0; fj < 4; fj++)
                    mma_bf16(acc[fi][fj], a[fi], bb[fj]);
        }
    }

    __syncthreads();
    __nv_bfloat16 (*Ct)[136] = (__nv_bfloat16(*)[136])gsm;
    #pragma unroll
    for (int fj = 0; fj < 4; fj++) {
        int gate0 = n0 + wn0 + fj*8 + 2*tq;
        float bv0 = b1[gate0]   + b2[gate0];
        float bv1 = b1[gate0+1] + b2[gate0+1];
        int ncol = wn0 + fj*8 + 2*tq;
        #pragma unroll
        for (int fi = 0; fi < 4; fi++) {
            #pragma unroll
            for (int p = 0; p < 2; p++) {
                int m = wm0 + fi*16 + g + p*8;
                *(uint32_t*)&Ct[m][ncol] =
                    packbf(acc[fi][fj][p*2+0] + bv0, acc[fi][fj][p*2+1] + bv1);
            }
        }
    }
    __syncthreads();
    #pragma unroll
    for (int i = 0; i < 8; i++) {
        int idx = i*256 + tid;
        int row = idx >> 4, c16 = idx & 15;
        uint4 v = *(uint4*)&Ct[row][c16*8];
        *(uint4*)(out + (size_t)(m0+row)*512 + n0 + c16*8) = v;
    }
}

// ---------------------------------------------------------------------------
// LSTM recurrence, 4-CTA cluster. Each CTA owns hidden slice
// j in [rank*32, rank*32+32) -> 128 gate rows as register fragments
// (32 regs/thread). Full h replicated in each CTA's smem; per-step h
// exchange via DSMEM b16 stores; rendezvous = 1 mbarrier/CTA (count 1024).
// G prefetched per step via cp.async double buffer. Grid (4,16,2)=128 CTAs.
// ---------------------------------------------------------------------------
__global__ void __cluster_dims__(4,1,1) __launch_bounds__(256,1)
lstm_k(const float* __restrict__ Whhf, const float* __restrict__ Whhb)
{
    extern __shared__ char lsm[];
    __nv_bfloat16* Gsm  = (__nv_bfloat16*)lsm;               // [2][16*512]  32768 B
    __nv_bfloat16* hbuf = (__nv_bfloat16*)(lsm + 32768);     // [2][16][132]  8448 B
    float (*zsm)[130]   = (float(*)[130])(lsm + 41216);      // [16][130]     8320 B
    uint64_t* mbar      = (uint64_t*)(lsm + 49536);          // 8 B

    const int tid  = threadIdx.x;
    const int lane = tid & 31;
    const int w    = tid >> 5;
    const int g    = lane >> 2, tq = lane & 3;
    const int rank = blockIdx.x & 3;
    const int dir  = blockIdx.z;
    const int nb0  = blockIdx.y * 16;
    const float* Whh = dir ? Whhb : Whhf;
    const __nv_bfloat16* G = g_G + (size_t)dir*65536*512;

    // Whh fragments: warp w owns local rows [w*16, w*16+16); 2 fj frags.
    // local row rl -> global gate row (rl>>5)*128 + rank*32 + (rl&31)
    uint32_t wb[2][8][2];
    #pragma unroll
    for (int fj = 0; fj < 2; fj++) {
        int rl = w*16 + fj*8 + g;
        int grow = (rl >> 5)*128 + rank*32 + (rl & 31);
        const float* wr = Whh + (size_t)grow*128;
        #pragma unroll
        for (int kt = 0; kt < 8; kt++) {
            wb[fj][kt][0] = packbf(wr[kt*16 + 2*tq    ], wr[kt*16 + 2*tq + 1]);
            wb[fj][kt][1] = packbf(wr[kt*16 + 2*tq + 8], wr[kt*16 + 2*tq + 9]);
        }
    }

    {
        uint32_t* hz = (uint32_t*)hbuf;
        for (int idx = tid; idx < 2*16*132/2; idx += 256) hz[idx] = 0u;
    }

    const uint32_t hbuf_u32 = smem_u32(hbuf);
    const uint32_t mbar_u32 = smem_u32(mbar);
    if (tid == 0) {
        asm volatile("mbarrier.init.shared.b64 [%0], %1;" :: "r"(mbar_u32), "r"(1024u) : "memory");
    }
    __syncthreads();
    asm volatile("barrier.cluster.arrive.aligned;\n\tbarrier.cluster.wait.aligned;" ::: "memory");

    // hoisted peer base addresses
    uint32_t rh[3], rm[3];
    {
        int pi = 0;
        #pragma unroll
        for (int p = 0; p < 4; p++) {
            if (p == rank) continue;
            asm volatile("mapa.shared::cluster.u32 %0, %1, %2;" : "=r"(rh[pi]) : "r"(hbuf_u32), "r"(p));
            asm volatile("mapa.shared::cluster.u32 %0, %1, %2;" : "=r"(rm[pi]) : "r"(mbar_u32), "r"(p));
            pi++;
        }
    }

    const int jj = tid & 31;
    const int mh = (tid >> 5) * 2;
    const int jglob = rank*32 + jj;
    float c[2] = {0.f, 0.f};

    auto gpre = [&](int buf, int t_idx) {
        #pragma unroll
        for (int i = 0; i < 4; i++) {
            int q = i*256 + tid;
            int m = q >> 6, ch = q & 63;
            cp16(smem_u32(Gsm + buf*8192 + m*512 + ch*8),
                 G + ((size_t)t_idx*256 + nb0 + m)*512 + ch*8);
        }
        cp_commit();
    };
    gpre(0, dir ? 255 : 0);

    for (int s = 0; s < 256; s++) {
        const int t   = dir ? (255 - s) : s;
        const int cur = s & 1, nxt = cur ^ 1;

        if (s < 255) gpre(nxt, dir ? (254 - s) : (s + 1));

        // ---- phase A: z = h @ Whh_slice^T (16 mma/warp) ----
        float acc[2][4];
        #pragma unroll
        for (int fj = 0; fj < 2; fj++)
            #pragma unroll
            for (int q = 0; q < 4; q++) acc[fj][q] = 0.f;

        const uint32_t* hb = (const uint32_t*)(hbuf + cur*16*132);  // row stride 66 u32
        #pragma unroll
        for (int kt = 0; kt < 8; kt++) {
            const int kp = kt*8;
            uint32_t a[4];
            a[0] = hb[(g  )*66 + kp + tq];
            a[1] = hb[(g+8)*66 + kp + tq];
            a[2] = hb[(g  )*66 + kp + tq + 4];
            a[3] = hb[(g+8)*66 + kp + tq + 4];
            #pragma unroll
            for (int fj = 0; fj < 2; fj++)
                mma_bf16(acc[fj], a, wb[fj][kt]);
        }
        #pragma unroll
        for (int fj = 0; fj < 2; fj++) {
            int nloc = w*16 + fj*8 + 2*tq;
            *(float2*)&zsm[g  ][nloc] = make_float2(acc[fj][0], acc[fj][1]);
            *(float2*)&zsm[g+8][nloc] = make_float2(acc[fj][2], acc[fj][3]);
        }
        if (s < 255) cp_wait1(); else cp_wait0();
        __syncthreads();

        // ---- phase B: gates for (2 m) x (jj) ----
        const __nv_bfloat16* Gc = Gsm + cur*8192;
        #pragma unroll
        for (int p2 = 0; p2 < 2; p2++) {
            int m = mh + p2;
            float ai = zsm[m][     jj] + __bfloat162float(Gc[m*512 +       jglob]);
            float af = zsm[m][32 + jj] + __bfloat162float(Gc[m*512 + 128 + jglob]);
            float ag = zsm[m][64 + jj] + __bfloat162float(Gc[m*512 + 256 + jglob]);
            float ao = zsm[m][96 + jj] + __bfloat162float(Gc[m*512 + 384 + jglob]);
            float iv = sig_fast(ai);
            float fv = sig_fast(af);
            float gv = tanh_fast(ag);
            float ov = sig_fast(ao);
            c[p2] = fv*c[p2] + iv*gv;
            float hv = ov * tanh_fast(c[p2]);
            __nv_bfloat16 hb16 = __float2bfloat16(hv);
            g_hcat[(size_t)(nb0+m)*65536 + t*256 + dir*128 + jglob] = hb16;
            uint32_t off2 = (uint32_t)((nxt*16 + m)*132 + jglob) * 2u;
            hbuf[(nxt*16 + m)*132 + jglob] = hb16;
            unsigned short hu = *(unsigned short*)&hb16;
            asm volatile("st.shared::cluster.b16 [%0], %1;" :: "r"(rh[0] + off2), "h"(hu) : "memory");
            asm volatile("st.shared::cluster.b16 [%0], %1;" :: "r"(rh[1] + off2), "h"(hu) : "memory");
            asm volatile("st.shared::cluster.b16 [%0], %1;" :: "r"(rh[2] + off2), "h"(hu) : "memory");
        }

        // rendezvous: arrive local (release) first, then the 3 peers, then wait
        asm volatile("mbarrier.arrive.release.cluster.shared::cta.b64 _, [%0];"
                     :: "r"(mbar_u32) : "memory");
        asm volatile("mbarrier.arrive.release.cluster.shared::cluster.b64 _, [%0];"
                     :: "r"(rm[0]) : "memory");
        asm volatile("mbarrier.arrive.release.cluster.shared::cluster.b64 _, [%0];"
                     :: "r"(rm[1]) : "memory");
        asm volatile("mbarrier.arrive.release.cluster.shared::cluster.b64 _, [%0];"
                     :: "r"(rm[2]) : "memory");
        {
            const uint32_t parity = (uint32_t)(s & 1);
            uint32_t done;
            asm volatile(
                "{\n\t.reg .pred p;\n\t"
                "mbarrier.try_wait.parity.acquire.cluster.shared::cta.b64 p, [%1], %2;\n\t"
                "selp.b32 %0, 1, 0, p;\n\t}"
                : "=r"(done) : "r"(mbar_u32), "r"(parity) : "memory");
            if (!done) {
                asm volatile(
                    "{\n\t.reg .pred P1;\n\t"
                    "WL_%=:\n\t"
                    "mbarrier.try_wait.parity.acquire.cluster.shared::cta.b64 P1, [%0], %1, 0x989680;\n\t"
                    "@P1 bra.uni WD_%=;\n\t"
                    "bra.uni WL_%=;\n\t"
                    "WD_%=:\n\t}"
                    :: "r"(mbar_u32), "r"(parity) : "memory");
            }
        }
    }
}

// ---------------------------------------------------------------------------
// FC1 split-K, bf16 mma, double-buffered (unchanged).
// ---------------------------------------------------------------------------
__global__ void fc1_mma_k()
{
    extern __shared__ uint32_t fsm[];
    uint32_t (*As)[20] = (uint32_t(*)[20])fsm;
    uint32_t (*Bs)[20] = (uint32_t(*)[20])(fsm + 2*256*20);

    const int tid  = threadIdx.x;
    const int lane = tid & 31;
    const int wid  = tid >> 5;
    const int g    = lane >> 2, tq = lane & 3;
    const int wm0  = (wid & 1) * 128;
    const int wn0  = (wid >> 1) * 32;
    const int k0   = blockIdx.x * 512;

    float acc[8][4][4];
    #pragma unroll
    for (int i = 0; i < 8; i++)
        #pragma unroll
        for (int j = 0; j < 4; j++)
            #pragma unroll
            for (int q = 0; q < 4; q++) acc[i][j][q] = 0.f;

    auto prefetch = [&](int b, int kt) {
        #pragma unroll
        for (int i = 0; i < 4; i++) {
            int l = i*256 + tid;
            int m = l >> 2, kq = l & 3;
            cp16(smem_u32(&As[b*256 + m][kq*4]),
                 g_hcat + (size_t)m*65536 + k0 + kt + kq*8);
        }
        #pragma unroll
        for (int i = 0; i < 2; i++) {
            int l = i*256 + tid;
            int n = l >> 2, kq = l & 3;
            cp16(smem_u32(&Bs[b*128 + n][kq*4]),
                 g_fc1wb16 + (size_t)n*65536 + k0 + kt + kq*8);
        }
    };

    prefetch(0, 0);
    cp_commit();
    cp_wait0();
    __syncthreads();

    for (int it = 0; it < 16; it++) {
        const int b = it & 1;
        if (it < 15) { prefetch(b^1, (it+1)*32); cp_commit(); }
        #pragma unroll
        for (int k16 = 0; k16 < 2; k16++) {
            const int kp = k16*8;
            uint32_t a[8][4], bb[4][2];
            #pragma unroll
            for (int fi = 0; fi < 8; fi++) {
                int r = b*256 + wm0 + fi*16;
                a[fi][0] = As[r+g  ][kp+tq];
                a[fi][1] = As[r+g+8][kp+tq];
                a[fi][2] = As[r+g  ][kp+tq+4];
                a[fi][3] = As[r+g+8][kp+tq+4];
            }
            #pragma unroll
            for (int fj = 0; fj < 4; fj++) {
                int cn = b*128 + wn0 + fj*8 + g;
                bb[fj][0] = Bs[cn][kp+tq];
                bb[fj][1] = Bs[cn][kp+tq+4];
            }
            #pragma unroll
            for (int fi = 0; fi < 8; fi++)
                #pragma unroll
                for (int fj = 0; fj < 4; fj++)
                    mma_bf16(acc[fi][fj], a[fi], bb[fj]);
        }
        if (it < 15) cp_wait0();
        __syncthreads();
    }

    float* part = g_fc1part + (size_t)blockIdx.x*256*128;
    #pragma unroll
    for (int fj = 0; fj < 4; fj++) {
        int n0 = wn0 + fj*8 + 2*tq;
        #pragma unroll
        for (int fi = 0; fi < 8; fi++) {
            #pragma unroll
            for (int p = 0; p < 2; p++) {
                int m = wm0 + fi*16 + g + p*8;
                *(float2*)(part + (size_t)m*128 + n0) =
                    make_float2(acc[fi][fj][p*2+0], acc[fi][fj][p*2+1]);
            }
        }
    }
}

__global__ void fc1_reduce_k(const float* __restrict__ fc1b)
{
    int idx = blockIdx.x*256 + threadIdx.x;
    int m = idx >> 7, h = idx & 127;
    float s = fc1b[h];
    #pragma unroll 8
    for (int kc = 0; kc < 128; kc++)
        s += g_fc1part[((size_t)kc*256 + m)*128 + h];
    g_z1[(size_t)m*128 + h] = fmaxf(s, 0.f);
}

__global__ void score_k(const float* __restrict__ fsw, const float* __restrict__ fsb,
                        float* __restrict__ out)
{
    __shared__ float w[128];
    __shared__ float fr[256];
    int tid = threadIdx.x;
    if (tid < 128) w[tid] = fsw[tid];
    __syncthreads();
    float acc = fsb[0];
    #pragma unroll 8
    for (int h = 0; h < 128; h++) acc += g_z1[(size_t)tid*128 + h] * w[h];
    float sc = 1.f / (1.f + expf(-acc)) * 4.f + 1.f;
    out[16 + tid] = sc;
    fr[tid] = sc;
    __syncthreads();
    if (tid < 16) {
        float s = 0.f;
        #pragma unroll
        for (int f = 0; f < 16; f++) s += fr[tid*16 + f];
        out[tid] = s * (1.f/16.f);
    }
}

// ---------------------------------------------------------------------------
extern "C" void kernel_launch(void* const* d_in, const int* in_sizes, int n_in,
                              void* d_out, int out_size)
{
    const float *audio,*w0,*b0,*w1,*b1,*w2,*b2,*w3,*b3;
    const float *Wihf,*Whhf,*bihf,*bhhf,*Wihb,*Whhb,*bihb,*bhhb;
    const float *fc1w,*fc1b,*fsw,*fsb;
    if (n_in >= 22 && in_sizes[1] == 144) {
        audio=(const float*)d_in[0];
        w0=(const float*)d_in[1];  b0=(const float*)d_in[2];
        w1=(const float*)d_in[3];  b1=(const float*)d_in[4];
        w2=(const float*)d_in[5];  b2=(const float*)d_in[6];
        w3=(const float*)d_in[7];  b3=(const float*)d_in[8];
        Wihf=(const float*)d_in[9];  Whhf=(const float*)d_in[10];
        bihf=(const float*)d_in[11]; bhhf=(const float*)d_in[12];
        Wihb=(const float*)d_in[13]; Whhb=(const float*)d_in[14];
        bihb=(const float*)d_in[15]; bhhb=(const float*)d_in[16];
        fc1w=(const float*)d_in[17]; fc1b=(const float*)d_in[18];
        fsw=(const float*)d_in[19];  fsb=(const float*)d_in[20];
    } else {
        audio=(const float*)d_in[0];
        w0=(const float*)d_in[2];  b0=(const float*)d_in[3];
        w1=(const float*)d_in[4];  b1=(const float*)d_in[5];
        w2=(const float*)d_in[6];  b2=(const float*)d_in[7];
        w3=(const float*)d_in[8];  b3=(const float*)d_in[9];
        Wihf=(const float*)d_in[10]; Whhf=(const float*)d_in[11];
        bihf=(const float*)d_in[12]; bhhf=(const float*)d_in[13];
        Wihb=(const float*)d_in[14]; Whhb=(const float*)d_in[15];
        bihb=(const float*)d_in[16]; bhhb=(const float*)d_in[17];
        fc1w=(const float*)d_in[18]; fc1b=(const float*)d_in[19];
        fsw=(const float*)d_in[20];  fsb=(const float*)d_in[21];
    }

    __nv_bfloat16 *x0,*x1,*x2,*xT,*wT1,*wT2,*wT3;
    cudaGetSymbolAddress((void**)&x0, g_x0);
    cudaGetSymbolAddress((void**)&x1, g_x1);
    cudaGetSymbolAddress((void**)&x2, g_x2);
    cudaGetSymbolAddress((void**)&xT, g_xT);
    cudaGetSymbolAddress((void**)&wT1, g_wT1);
    cudaGetSymbolAddress((void**)&wT2, g_wT2);
    cudaGetSymbolAddress((void**)&wT3, g_wT3);

    const int sc1 = (130*(27*8 +4) + 9*32 *(8 +4))*4;
    const int sc2 = (130*(9*16 +4) + 9*64 *(16+4))*4;
    const int sc3 = (130*(3*32 +4) + 9*128*(32+4))*4;
    const int sf  = 2*(256 + 128)*20*4;
    const int sg  = 3*2*128*20*4;
    const int slm = 49544;
    cudaFuncSetAttribute(conv_mma_k<16, 32,27,9,false>, cudaFuncAttributeMaxDynamicSharedMemorySize, sc1);
    cudaFuncSetAttribute(conv_mma_k<32, 64, 9,3,false>, cudaFuncAttributeMaxDynamicSharedMemorySize, sc2);
    cudaFuncSetAttribute(conv_mma_k<64,128, 3,1,true >, cudaFuncAttributeMaxDynamicSharedMemorySize, sc3);
    cudaFuncSetAttribute(fc1_mma_k, cudaFuncAttributeMaxDynamicSharedMemorySize, sf);
    cudaFuncSetAttribute(gemm_xw_k, cudaFuncAttributeMaxDynamicSharedMemorySize, sg);
    cudaFuncSetAttribute(lstm_k, cudaFuncAttributeMaxDynamicSharedMemorySize, slm);

    wtrans_k<<<(96768 + 255)/256, 256>>>(w1, w2, w3);
    prep_bf16_k<<<8192, 256>>>(Wihf, Wihb, fc1w);

    conv0_k<<<(BF*NT*27)/256, 256>>>(audio, w0, b0, x0);
    conv_mma_k<16, 32,27,9,false><<<dim3(2,BF), 256, sc1>>>(x0, wT1, b1, x1);
    conv_mma_k<32, 64, 9,3,false><<<dim3(2,BF), 256, sc2>>>(x1, wT2, b2, x2);
    conv_mma_k<64,128, 3,1,true ><<<dim3(2,BF), 256, sc3>>>(x2, wT3, b3, xT);

    gemm_xw_k<<<dim3(4,512,2), 256, sg>>>(xT, bihf, bhhf, bihb, bhhb);

    lstm_k<<<dim3(4,16,2), 256, slm>>>(Whhf, Whhb);

    fc1_mma_k<<<128, 256, sf>>>();
    fc1_reduce_k<<<128, 256>>>(fc1b);
    score_k<<<1, 256>>>(fsw, fsb, (float*)d_out);
}

// round 16
// speedup vs baseline: 1.6911x; 1.0596x over previous
#include <cuda_runtime.h>
#include <cuda_bf16.h>
#include <cstdint>
#include <math.h>

#define BF 256
#define NT 256

// ---------------------------------------------------------------------------
// Static scratch. All intermediates bf16.
// ---------------------------------------------------------------------------
__device__ __align__(16) __nv_bfloat16 g_x0[(size_t)BF*NT*27*16];
__device__ __align__(16) __nv_bfloat16 g_x1[(size_t)BF*NT*9*32];
__device__ __align__(16) __nv_bfloat16 g_x2[(size_t)BF*NT*3*64];
__device__ __align__(16) __nv_bfloat16 g_xT[(size_t)NT*BF*128];
__device__ __align__(16) __nv_bfloat16 g_hcat[(size_t)BF*65536];
__device__ __align__(16) float g_fc1part[(size_t)128*256*128];
__device__ __align__(16) float g_z1[(size_t)256*128];
__device__ __align__(16) __nv_bfloat16 g_wT1[9*32*16];
__device__ __align__(16) __nv_bfloat16 g_wT2[9*64*32];
__device__ __align__(16) __nv_bfloat16 g_wT3[9*128*64];
__device__ __align__(16) __nv_bfloat16 g_fc1wb16[(size_t)128*65536];

// ---------------------------------------------------------------------------
// helpers
// ---------------------------------------------------------------------------
__device__ __forceinline__ uint32_t packbf(float lo, float hi)
{
    __nv_bfloat162 h = __floats2bfloat162_rn(lo, hi);
    return *(uint32_t*)&h;
}
__device__ __forceinline__ void mma_bf16(float* d, const uint32_t* a, const uint32_t* b)
{
    asm("mma.sync.aligned.m16n8k16.row.col.f32.bf16.bf16.f32 "
        "{%0,%1,%2,%3}, {%4,%5,%6,%7}, {%8,%9}, {%0,%1,%2,%3};"
        : "+f"(d[0]), "+f"(d[1]), "+f"(d[2]), "+f"(d[3])
        : "r"(a[0]), "r"(a[1]), "r"(a[2]), "r"(a[3]), "r"(b[0]), "r"(b[1]));
}
__device__ __forceinline__ uint32_t smem_u32(const void* p)
{
    return (uint32_t)__cvta_generic_to_shared(p);
}
__device__ __forceinline__ void cp16(uint32_t dst, const void* src)
{
    asm volatile("cp.async.cg.shared.global [%0], [%1], 16;" :: "r"(dst), "l"(src));
}
__device__ __forceinline__ void cp16z(uint32_t dst, const void* src)
{
    asm volatile("cp.async.cg.shared.global [%0], [%1], 16, 0;" :: "r"(dst), "l"(src));
}
__device__ __forceinline__ void cp_commit() { asm volatile("cp.async.commit_group;"); }
__device__ __forceinline__ void cp_wait0()  { asm volatile("cp.async.wait_group 0;"); }
__device__ __forceinline__ void cp_wait1()  { asm volatile("cp.async.wait_group 1;"); }

__device__ __forceinline__ float tanh_fast(float x)
{
    float r;
    asm("tanh.approx.f32 %0, %1;" : "=f"(r) : "f"(x));
    return r;
}
__device__ __forceinline__ float sig_fast(float x)
{
    return fmaf(tanh_fast(0.5f*x), 0.5f, 0.5f);
}

// ---------------------------------------------------------------------------
// Prep kernels
// ---------------------------------------------------------------------------
__global__ void wtrans_k(const float* __restrict__ w1, const float* __restrict__ w2,
                         const float* __restrict__ w3)
{
    int idx = blockIdx.x*256 + threadIdx.x;
    const float* w; __nv_bfloat16* wT; int CIN, COUT;
    if (idx < 4608)        { w = w1; wT = g_wT1; CIN = 16; COUT = 32; }
    else if (idx < 23040)  { w = w2; wT = g_wT2; CIN = 32; COUT = 64; idx -= 4608; }
    else if (idx < 96768)  { w = w3; wT = g_wT3; CIN = 64; COUT = 128; idx -= 23040; }
    else return;
    int ci  = idx % CIN;
    int r   = idx / CIN;
    int co  = r % COUT;
    int tap = r / COUT;
    wT[idx] = __float2bfloat16(w[(co*CIN + ci)*9 + tap]);
}

__global__ void prep_bf16_k(const float* __restrict__ fc1w)
{
    const size_t total = 8388608;
    for (size_t i = (size_t)blockIdx.x*256 + threadIdx.x; i < total;
         i += (size_t)gridDim.x*256)
        g_fc1wb16[i] = __float2bfloat16(fc1w[i]);
}

// ---------------------------------------------------------------------------
// conv0: CIN=1 -> 16, direct. out NHWC bf16 [bf][t][27][16].
// ---------------------------------------------------------------------------
__global__ void conv0_k(const float* __restrict__ audio, const float* __restrict__ w,
                        const float* __restrict__ bias, __nv_bfloat16* __restrict__ out)
{
    __shared__ float wsm[9][16];
    __shared__ float bsm[16];
    int tid = threadIdx.x;
    if (tid < 144) wsm[tid % 9][tid / 9] = w[tid];
    if (tid < 16)  bsm[tid] = bias[tid];
    __syncthreads();

    size_t idx = (size_t)blockIdx.x*256 + tid;
    int wo = (int)(idx % 27);
    size_t r = idx / 27;
    int t  = (int)(r % NT);
    int bf = (int)(r / NT);

    float acc[16];
    #pragma unroll
    for (int co = 0; co < 16; co++) acc[co] = bsm[co];

    #pragma unroll
    for (int kh = 0; kh < 3; kh++) {
        int ti = t + kh - 1;
        if (ti < 0 || ti >= NT) continue;
        #pragma unroll
        for (int kw = 0; kw < 3; kw++) {
            int wc = 3*wo + kw - 1;
            if (wc < 0 || wc >= 81) continue;
            float v = audio[((size_t)bf*NT + ti)*81 + wc];
            #pragma unroll
            for (int co = 0; co < 16; co++) acc[co] += v * wsm[kh*3+kw][co];
        }
    }
    uint32_t* o = (uint32_t*)(out + idx*16);
    #pragma unroll
    for (int q = 0; q < 8; q++)
        o[q] = packbf(fmaxf(acc[q*2+0], 0.f), fmaxf(acc[q*2+1], 0.f));
}

// ---------------------------------------------------------------------------
// Conv, bf16 mma, single tile load per block (unchanged from R10).
// ---------------------------------------------------------------------------
template<int CIN,int COUT,int WIN,int WOUT,bool TOUT>
__global__ void conv_mma_k(const __nv_bfloat16* __restrict__ x,
                           const __nv_bfloat16* __restrict__ wT,
                           const float* __restrict__ bias,
                           __nv_bfloat16* __restrict__ out)
{
    constexpr int CU  = CIN/2;
    constexpr int LDT = WIN*CU + 4;
    constexpr int LDB = CU + 4;
    constexpr int NWN = COUT/32, WMW = 8/NWN, MFR = 128/WMW/16;
    constexpr int NK16 = CIN/16;
    extern __shared__ uint32_t sm[];
    uint32_t* At = sm;
    uint32_t* Bt = sm + 130*LDT;

    const int tid  = threadIdx.x;
    const int lane = tid & 31;
    const int wid  = tid >> 5;
    const int g    = lane >> 2, tq = lane & 3;
    const int wm0  = (wid % WMW) * (128/WMW);
    const int wn0  = (wid / WMW) * 32;
    const int t0   = blockIdx.x * 128;
    const int bf   = blockIdx.y;

    constexpr int ACH = WIN*CU/4;
    for (int l = tid; l < 130*ACH; l += 256) {
        int row = l / ACH, ch = l % ACH;
        int t_in = t0 + row - 1;
        uint32_t dst = smem_u32(At + row*LDT + ch*4);
        const __nv_bfloat16* src = x + ((size_t)bf*NT + (t_in < 0 ? 0 : (t_in >= NT ? NT-1 : t_in)))*WIN*CIN + ch*8;
        if (t_in >= 0 && t_in < NT) cp16(dst, src);
        else                        cp16z(dst, src);
    }
    constexpr int BCH = CU/4;
    for (int l = tid; l < 9*COUT*BCH; l += 256) {
        int r = l / BCH, ch = l % BCH;
        cp16(smem_u32(Bt + r*LDB + ch*4), wT + (size_t)r*CIN + ch*8);
    }
    cp_commit();
    cp_wait0();
    __syncthreads();

    float bv[4][2];
    #pragma unroll
    for (int fj = 0; fj < 4; fj++) {
        int co0 = wn0 + fj*8 + 2*tq;
        bv[fj][0] = bias[co0]; bv[fj][1] = bias[co0+1];
    }

    #pragma unroll 1
    for (int wo = 0; wo < WOUT; wo++) {
        float acc[MFR][4][4];
        #pragma unroll
        for (int i = 0; i < MFR; i++)
            #pragma unroll
            for (int j = 0; j < 4; j++)
                #pragma unroll
                for (int q = 0; q < 4; q++) acc[i][j][q] = 0.f;

        #pragma unroll
        for (int kh = 0; kh < 3; kh++) {
            #pragma unroll
            for (int kw = 0; kw < 3; kw++) {
                const int wc = 3*wo + kw - 1;
                if (wc < 0 || wc >= WIN) continue;
                const uint32_t* Btap = Bt + (size_t)(kh*3+kw)*COUT*LDB;
                #pragma unroll
                for (int k16 = 0; k16 < NK16; k16++) {
                    const int kp = k16*8;
                    const int ac = wc*CU + kp;
                    uint32_t a[MFR][4], b[4][2];
                    #pragma unroll
                    for (int fi = 0; fi < MFR; fi++) {
                        int r = wm0 + fi*16 + g + kh;
                        a[fi][0] = At[(r  )*LDT + ac + tq];
                        a[fi][1] = At[(r+8)*LDT + ac + tq];
                        a[fi][2] = At[(r  )*LDT + ac + tq + 4];
                        a[fi][3] = At[(r+8)*LDT + ac + tq + 4];
                    }
                    #pragma unroll
                    for (int fj = 0; fj < 4; fj++) {
                        int cn = wn0 + fj*8 + g;
                        b[fj][0] = Btap[cn*LDB + kp + tq];
                        b[fj][1] = Btap[cn*LDB + kp + tq + 4];
                    }
                    #pragma unroll
                    for (int fi = 0; fi < MFR; fi++)
                        #pragma unroll
                        for (int fj = 0; fj < 4; fj++)
                            mma_bf16(acc[fi][fj], a[fi], b[fj]);
                }
            }
        }

        #pragma unroll
        for (int fj = 0; fj < 4; fj++) {
            int co0 = wn0 + fj*8 + 2*tq;
            #pragma unroll
            for (int fi = 0; fi < MFR; fi++) {
                #pragma unroll
                for (int p = 0; p < 2; p++) {
                    int m = wm0 + fi*16 + g + p*8;
                    uint32_t v = packbf(fmaxf(acc[fi][fj][p*2+0] + bv[fj][0], 0.f),
                                        fmaxf(acc[fi][fj][p*2+1] + bv[fj][1], 0.f));
                    size_t base;
                    if (TOUT) base = ((size_t)(t0+m)*BF + bf)*COUT + co0;
                    else      base = (((size_t)bf*NT + (t0+m))*WOUT + wo)*COUT + co0;
                    *(uint32_t*)(out + base) = v;
                }
            }
        }
    }
}

// ---------------------------------------------------------------------------
// LSTM recurrence with FUSED input projection. 4-CTA cluster, grid (4,16,2).
// xts row stride = 136 bf16 (272 B, 16B-aligned for cp.async).
// ---------------------------------------------------------------------------
__global__ void __cluster_dims__(4,1,1) __launch_bounds__(256,1)
lstm_k(const float* __restrict__ Whhf, const float* __restrict__ Whhb,
       const float* __restrict__ Wihf, const float* __restrict__ Wihb,
       const float* __restrict__ bihf, const float* __restrict__ bhhf,
       const float* __restrict__ bihb, const float* __restrict__ bhhb)
{
    extern __shared__ char lsm[];
    __nv_bfloat16* xts  = (__nv_bfloat16*)lsm;             // [2][16][136]  8704
    __nv_bfloat16* hbuf = (__nv_bfloat16*)(lsm + 8704);    // [2][16][132]  8448
    float (*Gz)[130]    = (float(*)[130])(lsm + 17152);    // [2*16][130]  16640
    float (*zsm)[130]   = (float(*)[130])(lsm + 33792);    // [16][130]     8320
    uint64_t* mbar      = (uint64_t*)(lsm + 42112);        // 8

    const int tid  = threadIdx.x;
    const int lane = tid & 31;
    const int w    = tid >> 5;
    const int g    = lane >> 2, tq = lane & 3;
    const int rank = blockIdx.x & 3;
    const int dir  = blockIdx.z;
    const int nb0  = blockIdx.y * 16;
    const float* Whh = dir ? Whhb : Whhf;
    const float* Wih = dir ? Wihb : Wihf;
    const float* bih = dir ? bihb : bihf;
    const float* bhh = dir ? bhhb : bhhf;

    // fragments: warp w owns local gate rows [w*16, w*16+16)
    uint32_t wb[2][8][2], wbI[2][8][2];
    #pragma unroll
    for (int fj = 0; fj < 2; fj++) {
        int rl = w*16 + fj*8 + g;
        int grow = (rl >> 5)*128 + rank*32 + (rl & 31);
        const float* wr = Whh + (size_t)grow*128;
        const float* wi = Wih + (size_t)grow*128;
        #pragma unroll
        for (int kt = 0; kt < 8; kt++) {
            wb [fj][kt][0] = packbf(wr[kt*16 + 2*tq    ], wr[kt*16 + 2*tq + 1]);
            wb [fj][kt][1] = packbf(wr[kt*16 + 2*tq + 8], wr[kt*16 + 2*tq + 9]);
            wbI[fj][kt][0] = packbf(wi[kt*16 + 2*tq    ], wi[kt*16 + 2*tq + 1]);
            wbI[fj][kt][1] = packbf(wi[kt*16 + 2*tq + 8], wi[kt*16 + 2*tq + 9]);
        }
    }

    {
        uint32_t* hz = (uint32_t*)hbuf;
        for (int idx = tid; idx < 2*16*132/2; idx += 256) hz[idx] = 0u;
    }

    const uint32_t hbuf_u32 = smem_u32(hbuf);
    const uint32_t mbar_u32 = smem_u32(mbar);
    if (tid == 0) {
        asm volatile("mbarrier.init.shared.b64 [%0], %1;" :: "r"(mbar_u32), "r"(1024u) : "memory");
    }
    __syncthreads();
    asm volatile("barrier.cluster.arrive.aligned;\n\tbarrier.cluster.wait.aligned;" ::: "memory");

    uint32_t rh[3], rm[3];
    {
        int pi = 0;
        #pragma unroll
        for (int p = 0; p < 4; p++) {
            if (p == rank) continue;
            asm volatile("mapa.shared::cluster.u32 %0, %1, %2;" : "=r"(rh[pi]) : "r"(hbuf_u32), "r"(p));
            asm volatile("mapa.shared::cluster.u32 %0, %1, %2;" : "=r"(rm[pi]) : "r"(mbar_u32), "r"(p));
            pi++;
        }
    }

    const int jj = tid & 31;
    const int mh = (tid >> 5) * 2;
    const int jglob = rank*32 + jj;
    float c[2] = {0.f, 0.f};
    float bias_r[4];
    #pragma unroll
    for (int gt = 0; gt < 4; gt++)
        bias_r[gt] = bih[gt*128 + jglob] + bhh[gt*128 + jglob];

    // xT tile prefetch: one 16B chunk per thread (16 rows x 16 chunks)
    auto xpre = [&](int slot, int t_idx) {
        int m = tid >> 4, ch = tid & 15;
        cp16(smem_u32(xts + slot*16*136 + m*136 + ch*8),
             g_xT + ((size_t)t_idx*256 + nb0 + m)*128 + ch*8);
        cp_commit();
    };
    // input projection from xts[slot] into Gz[buf]
    auto gproj = [&](int slot, int buf) {
        float ga[2][4];
        #pragma unroll
        for (int fj = 0; fj < 2; fj++)
            #pragma unroll
            for (int q = 0; q < 4; q++) ga[fj][q] = 0.f;
        const uint32_t* xb = (const uint32_t*)(xts + slot*16*136);  // stride 68 u32
        #pragma unroll
        for (int kt = 0; kt < 8; kt++) {
            const int kp = kt*8;
            uint32_t a[4];
            a[0] = xb[(g  )*68 + kp + tq];
            a[1] = xb[(g+8)*68 + kp + tq];
            a[2] = xb[(g  )*68 + kp + tq + 4];
            a[3] = xb[(g+8)*68 + kp + tq + 4];
            #pragma unroll
            for (int fj = 0; fj < 2; fj++)
                mma_bf16(ga[fj], a, wbI[fj][kt]);
        }
        #pragma unroll
        for (int fj = 0; fj < 2; fj++) {
            int nloc = w*16 + fj*8 + 2*tq;
            *(float2*)&Gz[buf*16 + g  ][nloc] = make_float2(ga[fj][0], ga[fj][1]);
            *(float2*)&Gz[buf*16 + g+8][nloc] = make_float2(ga[fj][2], ga[fj][3]);
        }
    };

    // bootstrap: Gz[0] = proj(t(0)); preload xts[1]=t(1), xts[0]=t(2)
    const int tA = dir ? 255 : 0;
    xpre(0, tA);
    cp_wait0();
    __syncthreads();
    gproj(0, 0);
    __syncthreads();                       // gproj reads done before refill
    xpre(1, dir ? 254 : 1);
    xpre(0, dir ? 253 : 2);

    for (int s = 0; s < 256; s++) {
        const int t   = dir ? (255 - s) : s;
        const int cur = s & 1, nxt = cur ^ 1;

        // ---- phase A: recurrent z ----
        float acc[2][4];
        #pragma unroll
        for (int fj = 0; fj < 2; fj++)
            #pragma unroll
            for (int q = 0; q < 4; q++) acc[fj][q] = 0.f;

        const uint32_t* hb = (const uint32_t*)(hbuf + cur*16*132);
        #pragma unroll
        for (int kt = 0; kt < 8; kt++) {
            const int kp = kt*8;
            uint32_t a[4];
            a[0] = hb[(g  )*66 + kp + tq];
            a[1] = hb[(g+8)*66 + kp + tq];
            a[2] = hb[(g  )*66 + kp + tq + 4];
            a[3] = hb[(g+8)*66 + kp + tq + 4];
            #pragma unroll
            for (int fj = 0; fj < 2; fj++)
                mma_bf16(acc[fj], a, wb[fj][kt]);
        }
        #pragma unroll
        for (int fj = 0; fj < 2; fj++) {
            int nloc = w*16 + fj*8 + 2*tq;
            *(float2*)&zsm[g  ][nloc] = make_float2(acc[fj][0], acc[fj][1]);
            *(float2*)&zsm[g+8][nloc] = make_float2(acc[fj][2], acc[fj][3]);
        }

        // ---- input projection for t(s+1) ----
        if (s < 255) {
            cp_wait0();
            gproj((s+1) & 1, nxt);
        }
        __syncthreads();
        if (s < 253) xpre((s+1) & 1, dir ? (252 - s) : (s + 3));

        // ---- phase B ----
        const float (*Gzc)[130] = Gz + cur*16;
        #pragma unroll
        for (int p2 = 0; p2 < 2; p2++) {
            int m = mh + p2;
            float ai = zsm[m][     jj] + Gzc[m][     jj] + bias_r[0];
            float af = zsm[m][32 + jj] + Gzc[m][32 + jj] + bias_r[1];
            float ag = zsm[m][64 + jj] + Gzc[m][64 + jj] + bias_r[2];
            float ao = zsm[m][96 + jj] + Gzc[m][96 + jj] + bias_r[3];
            float iv = sig_fast(ai);
            float fv = sig_fast(af);
            float gv = tanh_fast(ag);
            float ov = sig_fast(ao);
            c[p2] = fv*c[p2] + iv*gv;
            float hv = ov * tanh_fast(c[p2]);
            __nv_bfloat16 hb16 = __float2bfloat16(hv);
            g_hcat[(size_t)(nb0+m)*65536 + t*256 + dir*128 + jglob] = hb16;
            uint32_t off2 = (uint32_t)((nxt*16 + m)*132 + jglob) * 2u;
            hbuf[(nxt*16 + m)*132 + jglob] = hb16;
            unsigned short hu = *(unsigned short*)&hb16;
            asm volatile("st.shared::cluster.b16 [%0], %1;" :: "r"(rh[0] + off2), "h"(hu) : "memory");
            asm volatile("st.shared::cluster.b16 [%0], %1;" :: "r"(rh[1] + off2), "h"(hu) : "memory");
            asm volatile("st.shared::cluster.b16 [%0], %1;" :: "r"(rh[2] + off2), "h"(hu) : "memory");
        }

        asm volatile("mbarrier.arrive.release.cluster.shared::cta.b64 _, [%0];"
                     :: "r"(mbar_u32) : "memory");
        asm volatile("mbarrier.arrive.release.cluster.shared::cluster.b64 _, [%0];"
                     :: "r"(rm[0]) : "memory");
        asm volatile("mbarrier.arrive.release.cluster.shared::cluster.b64 _, [%0];"
                     :: "r"(rm[1]) : "memory");
        asm volatile("mbarrier.arrive.release.cluster.shared::cluster.b64 _, [%0];"
                     :: "r"(rm[2]) : "memory");
        {
            const uint32_t parity = (uint32_t)(s & 1);
            uint32_t done;
            asm volatile(
                "{\n\t.reg .pred p;\n\t"
                "mbarrier.try_wait.parity.acquire.cluster.shared::cta.b64 p, [%1], %2;\n\t"
                "selp.b32 %0, 1, 0, p;\n\t}"
                : "=r"(done) : "r"(mbar_u32), "r"(parity) : "memory");
            if (!done) {
                asm volatile(
                    "{\n\t.reg .pred P1;\n\t"
                    "WL_%=:\n\t"
                    "mbarrier.try_wait.parity.acquire.cluster.shared::cta.b64 P1, [%0], %1, 0x989680;\n\t"
                    "@P1 bra.uni WD_%=;\n\t"
                    "bra.uni WL_%=;\n\t"
                    "WD_%=:\n\t}"
                    :: "r"(mbar_u32), "r"(parity) : "memory");
            }
        }
    }
}

// ---------------------------------------------------------------------------
// FC1 split-K, bf16 mma, double-buffered (unchanged).
// ---------------------------------------------------------------------------
__global__ void fc1_mma_k()
{
    extern __shared__ uint32_t fsm[];
    uint32_t (*As)[20] = (uint32_t(*)[20])fsm;
    uint32_t (*Bs)[20] = (uint32_t(*)[20])(fsm + 2*256*20);

    const int tid  = threadIdx.x;
    const int lane = tid & 31;
    const int wid  = tid >> 5;
    const int g    = lane >> 2, tq = lane & 3;
    const int wm0  = (wid & 1) * 128;
    const int wn0  = (wid >> 1) * 32;
    const int k0   = blockIdx.x * 512;

    float acc[8][4][4];
    #pragma unroll
    for (int i = 0; i < 8; i++)
        #pragma unroll
        for (int j = 0; j < 4; j++)
            #pragma unroll
            for (int q = 0; q < 4; q++) acc[i][j][q] = 0.f;

    auto prefetch = [&](int b, int kt) {
        #pragma unroll
        for (int i = 0; i < 4; i++) {
            int l = i*256 + tid;
            int m = l >> 2, kq = l & 3;
            cp16(smem_u32(&As[b*256 + m][kq*4]),
                 g_hcat + (size_t)m*65536 + k0 + kt + kq*8);
        }
        #pragma unroll
        for (int i = 0; i < 2; i++) {
            int l = i*256 + tid;
            int n = l >> 2, kq = l & 3;
            cp16(smem_u32(&Bs[b*128 + n][kq*4]),
                 g_fc1wb16 + (size_t)n*65536 + k0 + kt + kq*8);
        }
    };

    prefetch(0, 0);
    cp_commit();
    cp_wait0();
    __syncthreads();

    for (int it = 0; it < 16; it++) {
        const int b = it & 1;
        if (it < 15) { prefetch(b^1, (it+1)*32); cp_commit(); }
        #pragma unroll
        for (int k16 = 0; k16 < 2; k16++) {
            const int kp = k16*8;
            uint32_t a[8][4], bb[4][2];
            #pragma unroll
            for (int fi = 0; fi < 8; fi++) {
                int r = b*256 + wm0 + fi*16;
                a[fi][0] = As[r+g  ][kp+tq];
                a[fi][1] = As[r+g+8][kp+tq];
                a[fi][2] = As[r+g  ][kp+tq+4];
                a[fi][3] = As[r+g+8][kp+tq+4];
            }
            #pragma unroll
            for (int fj = 0; fj < 4; fj++) {
                int cn = b*128 + wn0 + fj*8 + g;
                bb[fj][0] = Bs[cn][kp+tq];
                bb[fj][1] = Bs[cn][kp+tq+4];
            }
            #pragma unroll
            for (int fi = 0; fi < 8; fi++)
                #pragma unroll
                for (int fj = 0; fj < 4; fj++)
                    mma_bf16(acc[fi][fj], a[fi], bb[fj]);
        }
        if (it < 15) cp_wait0();
        __syncthreads();
    }

    float* part = g_fc1part + (size_t)blockIdx.x*256*128;
    #pragma unroll
    for (int fj = 0; fj < 4; fj++) {
        int n0 = wn0 + fj*8 + 2*tq;
        #pragma unroll
        for (int fi = 0; fi < 8; fi++) {
            #pragma unroll
            for (int p = 0; p < 2; p++) {
                int m = wm0 + fi*16 + g + p*8;
                *(float2*)(part + (size_t)m*128 + n0) =
                    make_float2(acc[fi][fj][p*2+0], acc[fi][fj][p*2+1]);
            }
        }
    }
}

__global__ void fc1_reduce_k(const float* __restrict__ fc1b)
{
    int idx = blockIdx.x*256 + threadIdx.x;
    int m = idx >> 7, h = idx & 127;
    float s = fc1b[h];
    #pragma unroll 8
    for (int kc = 0; kc < 128; kc++)
        s += g_fc1part[((size_t)kc*256 + m)*128 + h];
    g_z1[(size_t)m*128 + h] = fmaxf(s, 0.f);
}

__global__ void score_k(const float* __restrict__ fsw, const float* __restrict__ fsb,
                        float* __restrict__ out)
{
    __shared__ float w[128];
    __shared__ float fr[256];
    int tid = threadIdx.x;
    if (tid < 128) w[tid] = fsw[tid];
    __syncthreads();
    float acc = fsb[0];
    #pragma unroll 8
    for (int h = 0; h < 128; h++) acc += g_z1[(size_t)tid*128 + h] * w[h];
    float sc = 1.f / (1.f + expf(-acc)) * 4.f + 1.f;
    out[16 + tid] = sc;
    fr[tid] = sc;
    __syncthreads();
    if (tid < 16) {
        float s = 0.f;
        #pragma unroll
        for (int f = 0; f < 16; f++) s += fr[tid*16 + f];
        out[tid] = s * (1.f/16.f);
    }
}

// ---------------------------------------------------------------------------
extern "C" void kernel_launch(void* const* d_in, const int* in_sizes, int n_in,
                              void* d_out, int out_size)
{
    const float *audio,*w0,*b0,*w1,*b1,*w2,*b2,*w3,*b3;
    const float *Wihf,*Whhf,*bihf,*bhhf,*Wihb,*Whhb,*bihb,*bhhb;
    const float *fc1w,*fc1b,*fsw,*fsb;
    if (n_in >= 22 && in_sizes[1] == 144) {
        audio=(const float*)d_in[0];
        w0=(const float*)d_in[1];  b0=(const float*)d_in[2];
        w1=(const float*)d_in[3];  b1=(const float*)d_in[4];
        w2=(const float*)d_in[5];  b2=(const float*)d_in[6];
        w3=(const float*)d_in[7];  b3=(const float*)d_in[8];
        Wihf=(const float*)d_in[9];  Whhf=(const float*)d_in[10];
        bihf=(const float*)d_in[11]; bhhf=(const float*)d_in[12];
        Wihb=(const float*)d_in[13]; Whhb=(const float*)d_in[14];
        bihb=(const float*)d_in[15]; bhhb=(const float*)d_in[16];
        fc1w=(const float*)d_in[17]; fc1b=(const float*)d_in[18];
        fsw=(const float*)d_in[19];  fsb=(const float*)d_in[20];
    } else {
        audio=(const float*)d_in[0];
        w0=(const float*)d_in[2];  b0=(const float*)d_in[3];
        w1=(const float*)d_in[4];  b1=(const float*)d_in[5];
        w2=(const float*)d_in[6];  b2=(const float*)d_in[7];
        w3=(const float*)d_in[8];  b3=(const float*)d_in[9];
        Wihf=(const float*)d_in[10]; Whhf=(const float*)d_in[11];
        bihf=(const float*)d_in[12]; bhhf=(const float*)d_in[13];
        Wihb=(const float*)d_in[14]; Whhb=(const float*)d_in[15];
        bihb=(const float*)d_in[16]; bhhb=(const float*)d_in[17];
        fc1w=(const float*)d_in[18]; fc1b=(const float*)d_in[19];
        fsw=(const float*)d_in[20];  fsb=(const float*)d_in[21];
    }

    __nv_bfloat16 *x0,*x1,*x2,*xT,*wT1,*wT2,*wT3;
    cudaGetSymbolAddress((void**)&x0, g_x0);
    cudaGetSymbolAddress((void**)&x1, g_x1);
    cudaGetSymbolAddress((void**)&x2, g_x2);
    cudaGetSymbolAddress((void**)&xT, g_xT);
    cudaGetSymbolAddress((void**)&wT1, g_wT1);
    cudaGetSymbolAddress((void**)&wT2, g_wT2);
    cudaGetSymbolAddress((void**)&wT3, g_wT3);

    const int sc1 = (130*(27*8 +4) + 9*32 *(8 +4))*4;
    const int sc2 = (130*(9*16 +4) + 9*64 *(16+4))*4;
    const int sc3 = (130*(3*32 +4) + 9*128*(32+4))*4;
    const int sf  = 2*(256 + 128)*20*4;
    const int slm = 42120;
    cudaFuncSetAttribute(conv_mma_k<16, 32,27,9,false>, cudaFuncAttributeMaxDynamicSharedMemorySize, sc1);
    cudaFuncSetAttribute(conv_mma_k<32, 64, 9,3,false>, cudaFuncAttributeMaxDynamicSharedMemorySize, sc2);
    cudaFuncSetAttribute(conv_mma_k<64,128, 3,1,true >, cudaFuncAttributeMaxDynamicSharedMemorySize, sc3);
    cudaFuncSetAttribute(fc1_mma_k, cudaFuncAttributeMaxDynamicSharedMemorySize, sf);
    cudaFuncSetAttribute(lstm_k, cudaFuncAttributeMaxDynamicSharedMemorySize, slm);

    wtrans_k<<<(96768 + 255)/256, 256>>>(w1, w2, w3);
    prep_bf16_k<<<4096, 256>>>(fc1w);

    conv0_k<<<(BF*NT*27)/256, 256>>>(audio, w0, b0, x0);
    conv_mma_k<16, 32,27,9,false><<<dim3(2,BF), 256, sc1>>>(x0, wT1, b1, x1);
    conv_mma_k<32, 64, 9,3,false><<<dim3(2,BF), 256, sc2>>>(x1, wT2, b2, x2);
    conv_mma_k<64,128, 3,1,true ><<<dim3(2,BF), 256, sc3>>>(x2, wT3, b3, xT);

    lstm_k<<<dim3(4,16,2), 256, slm>>>(Whhf, Whhb, Wihf, Wihb,
                                       bihf, bhhf, bihb, bhhb);

    fc1_mma_k<<<128, 256, sf>>>();
    fc1_reduce_k<<<128, 256>>>(fc1b);
    score_k<<<1, 256>>>(fsw, fsb, (float*)d_out);
}

// round 17
// speedup vs baseline: 1.7011x; 1.0059x over previous
#include <cuda_runtime.h>
#include <cuda_bf16.h>
#include <cstdint>
#include <math.h>

#define BF 256
#define NT 256

// ---------------------------------------------------------------------------
// Static scratch. All intermediates bf16.
// ---------------------------------------------------------------------------
__device__ __align__(16) __nv_bfloat16 g_x0[(size_t)BF*NT*27*16];
__device__ __align__(16) __nv_bfloat16 g_x1[(size_t)BF*NT*9*32];
__device__ __align__(16) __nv_bfloat16 g_x2[(size_t)BF*NT*3*64];
__device__ __align__(16) __nv_bfloat16 g_xT[(size_t)NT*BF*128];
__device__ __align__(16) __nv_bfloat16 g_hcat[(size_t)BF*65536];
__device__ __align__(16) float g_fc1part[(size_t)128*256*128];
__device__ __align__(16) float g_z1[(size_t)256*128];
__device__ __align__(16) __nv_bfloat16 g_wT1[9*32*16];
__device__ __align__(16) __nv_bfloat16 g_wT2[9*64*32];
__device__ __align__(16) __nv_bfloat16 g_wT3[9*128*64];
__device__ __align__(16) __nv_bfloat16 g_fc1wb16[(size_t)128*65536];

// ---------------------------------------------------------------------------
// helpers
// ---------------------------------------------------------------------------
__device__ __forceinline__ uint32_t packbf(float lo, float hi)
{
    __nv_bfloat162 h = __floats2bfloat162_rn(lo, hi);
    return *(uint32_t*)&h;
}
__device__ __forceinline__ void mma_bf16(float* d, const uint32_t* a, const uint32_t* b)
{
    asm("mma.sync.aligned.m16n8k16.row.col.f32.bf16.bf16.f32 "
        "{%0,%1,%2,%3}, {%4,%5,%6,%7}, {%8,%9}, {%0,%1,%2,%3};"
        : "+f"(d[0]), "+f"(d[1]), "+f"(d[2]), "+f"(d[3])
        : "r"(a[0]), "r"(a[1]), "r"(a[2]), "r"(a[3]), "r"(b[0]), "r"(b[1]));
}
__device__ __forceinline__ uint32_t smem_u32(const void* p)
{
    return (uint32_t)__cvta_generic_to_shared(p);
}
__device__ __forceinline__ void cp16(uint32_t dst, const void* src)
{
    asm volatile("cp.async.cg.shared.global [%0], [%1], 16;" :: "r"(dst), "l"(src));
}
__device__ __forceinline__ void cp16z(uint32_t dst, const void* src)
{
    asm volatile("cp.async.cg.shared.global [%0], [%1], 16, 0;" :: "r"(dst), "l"(src));
}
__device__ __forceinline__ void cp_commit() { asm volatile("cp.async.commit_group;"); }
__device__ __forceinline__ void cp_wait0()  { asm volatile("cp.async.wait_group 0;"); }

__device__ __forceinline__ float tanh_fast(float x)
{
    float r;
    asm("tanh.approx.f32 %0, %1;" : "=f"(r) : "f"(x));
    return r;
}
__device__ __forceinline__ float sig_fast(float x)
{
    return fmaf(tanh_fast(0.5f*x), 0.5f, 0.5f);
}

// ---------------------------------------------------------------------------
// Prep kernels
// ---------------------------------------------------------------------------
__global__ void wtrans_k(const float* __restrict__ w1, const float* __restrict__ w2,
                         const float* __restrict__ w3)
{
    int idx = blockIdx.x*256 + threadIdx.x;
    const float* w; __nv_bfloat16* wT; int CIN, COUT;
    if (idx < 4608)        { w = w1; wT = g_wT1; CIN = 16; COUT = 32; }
    else if (idx < 23040)  { w = w2; wT = g_wT2; CIN = 32; COUT = 64; idx -= 4608; }
    else if (idx < 96768)  { w = w3; wT = g_wT3; CIN = 64; COUT = 128; idx -= 23040; }
    else return;
    int ci  = idx % CIN;
    int r   = idx / CIN;
    int co  = r % COUT;
    int tap = r / COUT;
    wT[idx] = __float2bfloat16(w[(co*CIN + ci)*9 + tap]);
}

__global__ void prep_bf16_k(const float* __restrict__ fc1w)
{
    const size_t total = 8388608;
    for (size_t i = (size_t)blockIdx.x*256 + threadIdx.x; i < total;
         i += (size_t)gridDim.x*256)
        g_fc1wb16[i] = __float2bfloat16(fc1w[i]);
}

// ---------------------------------------------------------------------------
// conv0: CIN=1 -> 16, direct. out NHWC bf16 [bf][t][27][16].
// ---------------------------------------------------------------------------
__global__ void conv0_k(const float* __restrict__ audio, const float* __restrict__ w,
                        const float* __restrict__ bias, __nv_bfloat16* __restrict__ out)
{
    __shared__ float wsm[9][16];
    __shared__ float bsm[16];
    int tid = threadIdx.x;
    if (tid < 144) wsm[tid % 9][tid / 9] = w[tid];
    if (tid < 16)  bsm[tid] = bias[tid];
    __syncthreads();

    size_t idx = (size_t)blockIdx.x*256 + tid;
    int wo = (int)(idx % 27);
    size_t r = idx / 27;
    int t  = (int)(r % NT);
    int bf = (int)(r / NT);

    float acc[16];
    #pragma unroll
    for (int co = 0; co < 16; co++) acc[co] = bsm[co];

    #pragma unroll
    for (int kh = 0; kh < 3; kh++) {
        int ti = t + kh - 1;
        if (ti < 0 || ti >= NT) continue;
        #pragma unroll
        for (int kw = 0; kw < 3; kw++) {
            int wc = 3*wo + kw - 1;
            if (wc < 0 || wc >= 81) continue;
            float v = audio[((size_t)bf*NT + ti)*81 + wc];
            #pragma unroll
            for (int co = 0; co < 16; co++) acc[co] += v * wsm[kh*3+kw][co];
        }
    }
    uint32_t* o = (uint32_t*)(out + idx*16);
    #pragma unroll
    for (int q = 0; q < 8; q++)
        o[q] = packbf(fmaxf(acc[q*2+0], 0.f), fmaxf(acc[q*2+1], 0.f));
}

// ---------------------------------------------------------------------------
// Conv, bf16 mma. Generalized: BM t-rows/block, NWN n-warps of WNC cols,
// taps kw in [KWLO,KWHI], COUT split across NSPLIT blocks.
// grid: NSPLIT==1 ? (NT/BM, BF) : (NT/BM, NSPLIT, BF).
// ---------------------------------------------------------------------------
template<int CIN,int COUT,int WIN,int WOUT,int BM,int NWN,int WNC,
         int KWLO,int KWHI,int NSPLIT,bool TOUT>
__global__ void conv_mma_k(const __nv_bfloat16* __restrict__ x,
                           const __nv_bfloat16* __restrict__ wT,
                           const float* __restrict__ bias,
                           __nv_bfloat16* __restrict__ out)
{
    constexpr int CU   = CIN/2;
    constexpr int LDT  = WIN*CU + 4;
    constexpr int LDB  = CU + 4;
    constexpr int NWM  = 8/NWN;
    constexpr int MFR  = BM/NWM/16;
    constexpr int FJC  = WNC/8;
    constexpr int NKW  = KWHI - KWLO + 1;
    constexpr int NTAP = 3*NKW;
    constexpr int CBLK = COUT/NSPLIT;
    constexpr int NK16 = CIN/16;
    extern __shared__ uint32_t sm[];
    uint32_t* At = sm;                     // [(BM+2)][LDT]
    uint32_t* Bt = sm + (BM+2)*LDT;        // [NTAP][CBLK][LDB]

    const int tid  = threadIdx.x;
    const int lane = tid & 31;
    const int wid  = tid >> 5;
    const int g    = lane >> 2, tq = lane & 3;
    const int wm0  = (wid % NWM) * (BM/NWM);
    const int wn0  = (wid / NWM) * WNC;
    const int t0   = blockIdx.x * BM;
    const int nblk = (NSPLIT > 1) ? blockIdx.y : 0;
    const int bf   = (NSPLIT > 1) ? blockIdx.z : blockIdx.y;

    constexpr int ACH = WIN*CU/4;
    for (int l = tid; l < (BM+2)*ACH; l += 256) {
        int row = l / ACH, ch = l % ACH;
        int t_in = t0 + row - 1;
        uint32_t dst = smem_u32(At + row*LDT + ch*4);
        const __nv_bfloat16* src = x + ((size_t)bf*NT + (t_in < 0 ? 0 : (t_in >= NT ? NT-1 : t_in)))*WIN*CIN + ch*8;
        if (t_in >= 0 && t_in < NT) cp16(dst, src);
        else                        cp16z(dst, src);
    }
    constexpr int BCH = CU/4;
    for (int l = tid; l < NTAP*CBLK*BCH; l += 256) {
        int r = l / BCH, ch = l % BCH;
        int tt = r / CBLK, co = r % CBLK;
        int kh = tt / NKW, kw = tt % NKW + KWLO;
        cp16(smem_u32(Bt + r*LDB + ch*4),
             wT + ((size_t)(kh*3 + kw)*COUT + nblk*CBLK + co)*CIN + ch*8);
    }
    cp_commit();
    cp_wait0();
    __syncthreads();

    float bv[FJC][2];
    #pragma unroll
    for (int fj = 0; fj < FJC; fj++) {
        int co0 = nblk*CBLK + wn0 + fj*8 + 2*tq;
        bv[fj][0] = bias[co0]; bv[fj][1] = bias[co0+1];
    }

    #pragma unroll 1
    for (int wo = 0; wo < WOUT; wo++) {
        float acc[MFR][FJC][4];
        #pragma unroll
        for (int i = 0; i < MFR; i++)
            #pragma unroll
            for (int j = 0; j < FJC; j++)
                #pragma unroll
                for (int q = 0; q < 4; q++) acc[i][j][q] = 0.f;

        #pragma unroll
        for (int kh = 0; kh < 3; kh++) {
            #pragma unroll
            for (int kw = KWLO; kw <= KWHI; kw++) {
                const int wc = 3*wo + kw - 1;
                if (wc < 0 || wc >= WIN) continue;
                const uint32_t* Btap = Bt + (size_t)(kh*NKW + (kw-KWLO))*CBLK*LDB;
                #pragma unroll
                for (int k16 = 0; k16 < NK16; k16++) {
                    const int kp = k16*8;
                    const int ac = wc*CU + kp;
                    uint32_t a[MFR][4], b[FJC][2];
                    #pragma unroll
                    for (int fi = 0; fi < MFR; fi++) {
                        int r = wm0 + fi*16 + g + kh;
                        a[fi][0] = At[(r  )*LDT + ac + tq];
                        a[fi][1] = At[(r+8)*LDT + ac + tq];
                        a[fi][2] = At[(r  )*LDT + ac + tq + 4];
                        a[fi][3] = At[(r+8)*LDT + ac + tq + 4];
                    }
                    #pragma unroll
                    for (int fj = 0; fj < FJC; fj++) {
                        int cn = wn0 + fj*8 + g;
                        b[fj][0] = Btap[cn*LDB + kp + tq];
                        b[fj][1] = Btap[cn*LDB + kp + tq + 4];
                    }
                    #pragma unroll
                    for (int fi = 0; fi < MFR; fi++)
                        #pragma unroll
                        for (int fj = 0; fj < FJC; fj++)
                            mma_bf16(acc[fi][fj], a[fi], b[fj]);
                }
            }
        }

        #pragma unroll
        for (int fj = 0; fj < FJC; fj++) {
            int co0 = nblk*CBLK + wn0 + fj*8 + 2*tq;
            #pragma unroll
            for (int fi = 0; fi < MFR; fi++) {
                #pragma unroll
                for (int p = 0; p < 2; p++) {
                    int m = wm0 + fi*16 + g + p*8;
                    uint32_t v = packbf(fmaxf(acc[fi][fj][p*2+0] + bv[fj][0], 0.f),
                                        fmaxf(acc[fi][fj][p*2+1] + bv[fj][1], 0.f));
                    size_t base;
                    if (TOUT) base = ((size_t)(t0+m)*BF + bf)*COUT + co0;
                    else      base = (((size_t)bf*NT + (t0+m))*WOUT + wo)*COUT + co0;
                    *(uint32_t*)(out + base) = v;
                }
            }
        }
    }
}

// ---------------------------------------------------------------------------
// LSTM recurrence with FUSED input projection (unchanged from R16).
// ---------------------------------------------------------------------------
__global__ void __cluster_dims__(4,1,1) __launch_bounds__(256,1)
lstm_k(const float* __restrict__ Whhf, const float* __restrict__ Whhb,
       const float* __restrict__ Wihf, const float* __restrict__ Wihb,
       const float* __restrict__ bihf, const float* __restrict__ bhhf,
       const float* __restrict__ bihb, const float* __restrict__ bhhb)
{
    extern __shared__ char lsm[];
    __nv_bfloat16* xts  = (__nv_bfloat16*)lsm;             // [2][16][136]  8704
    __nv_bfloat16* hbuf = (__nv_bfloat16*)(lsm + 8704);    // [2][16][132]  8448
    float (*Gz)[130]    = (float(*)[130])(lsm + 17152);    // [2*16][130]  16640
    float (*zsm)[130]   = (float(*)[130])(lsm + 33792);    // [16][130]     8320
    uint64_t* mbar      = (uint64_t*)(lsm + 42112);        // 8

    const int tid  = threadIdx.x;
    const int lane = tid & 31;
    const int w    = tid >> 5;
    const int g    = lane >> 2, tq = lane & 3;
    const int rank = blockIdx.x & 3;
    const int dir  = blockIdx.z;
    const int nb0  = blockIdx.y * 16;
    const float* Whh = dir ? Whhb : Whhf;
    const float* Wih = dir ? Wihb : Wihf;
    const float* bih = dir ? bihb : bihf;
    const float* bhh = dir ? bhhb : bhhf;

    uint32_t wb[2][8][2], wbI[2][8][2];
    #pragma unroll
    for (int fj = 0; fj < 2; fj++) {
        int rl = w*16 + fj*8 + g;
        int grow = (rl >> 5)*128 + rank*32 + (rl & 31);
        const float* wr = Whh + (size_t)grow*128;
        const float* wi = Wih + (size_t)grow*128;
        #pragma unroll
        for (int kt = 0; kt < 8; kt++) {
            wb [fj][kt][0] = packbf(wr[kt*16 + 2*tq    ], wr[kt*16 + 2*tq + 1]);
            wb [fj][kt][1] = packbf(wr[kt*16 + 2*tq + 8], wr[kt*16 + 2*tq + 9]);
            wbI[fj][kt][0] = packbf(wi[kt*16 + 2*tq    ], wi[kt*16 + 2*tq + 1]);
            wbI[fj][kt][1] = packbf(wi[kt*16 + 2*tq + 8], wi[kt*16 + 2*tq + 9]);
        }
    }

    {
        uint32_t* hz = (uint32_t*)hbuf;
        for (int idx = tid; idx < 2*16*132/2; idx += 256) hz[idx] = 0u;
    }

    const uint32_t hbuf_u32 = smem_u32(hbuf);
    const uint32_t mbar_u32 = smem_u32(mbar);
    if (tid == 0) {
        asm volatile("mbarrier.init.shared.b64 [%0], %1;" :: "r"(mbar_u32), "r"(1024u) : "memory");
    }
    __syncthreads();
    asm volatile("barrier.cluster.arrive.aligned;\n\tbarrier.cluster.wait.aligned;" ::: "memory");

    uint32_t rh[3], rm[3];
    {
        int pi = 0;
        #pragma unroll
        for (int p = 0; p < 4; p++) {
            if (p == rank) continue;
            asm volatile("mapa.shared::cluster.u32 %0, %1, %2;" : "=r"(rh[pi]) : "r"(hbuf_u32), "r"(p));
            asm volatile("mapa.shared::cluster.u32 %0, %1, %2;" : "=r"(rm[pi]) : "r"(mbar_u32), "r"(p));
            pi++;
        }
    }

    const int jj = tid & 31;
    const int mh = (tid >> 5) * 2;
    const int jglob = rank*32 + jj;
    float c[2] = {0.f, 0.f};
    float bias_r[4];
    #pragma unroll
    for (int gt = 0; gt < 4; gt++)
        bias_r[gt] = bih[gt*128 + jglob] + bhh[gt*128 + jglob];

    auto xpre = [&](int slot, int t_idx) {
        int m = tid >> 4, ch = tid & 15;
        cp16(smem_u32(xts + slot*16*136 + m*136 + ch*8),
             g_xT + ((size_t)t_idx*256 + nb0 + m)*128 + ch*8);
        cp_commit();
    };
    auto gproj = [&](int slot, int buf) {
        float ga[2][4];
        #pragma unroll
        for (int fj = 0; fj < 2; fj++)
            #pragma unroll
            for (int q = 0; q < 4; q++) ga[fj][q] = 0.f;
        const uint32_t* xb = (const uint32_t*)(xts + slot*16*136);
        #pragma unroll
        for (int kt = 0; kt < 8; kt++) {
            const int kp = kt*8;
            uint32_t a[4];
            a[0] = xb[(g  )*68 + kp + tq];
            a[1] = xb[(g+8)*68 + kp + tq];
            a[2] = xb[(g  )*68 + kp + tq + 4];
            a[3] = xb[(g+8)*68 + kp + tq + 4];
            #pragma unroll
            for (int fj = 0; fj < 2; fj++)
                mma_bf16(ga[fj], a, wbI[fj][kt]);
        }
        #pragma unroll
        for (int fj = 0; fj < 2; fj++) {
            int nloc = w*16 + fj*8 + 2*tq;
            *(float2*)&Gz[buf*16 + g  ][nloc] = make_float2(ga[fj][0], ga[fj][1]);
            *(float2*)&Gz[buf*16 + g+8][nloc] = make_float2(ga[fj][2], ga[fj][3]);
        }
    };

    const int tA = dir ? 255 : 0;
    xpre(0, tA);
    cp_wait0();
    __syncthreads();
    gproj(0, 0);
    __syncthreads();
    xpre(1, dir ? 254 : 1);
    xpre(0, dir ? 253 : 2);

    for (int s = 0; s < 256; s++) {
        const int t   = dir ? (255 - s) : s;
        const int cur = s & 1, nxt = cur ^ 1;

        float acc[2][4];
        #pragma unroll
        for (int fj = 0; fj < 2; fj++)
            #pragma unroll
            for (int q = 0; q < 4; q++) acc[fj][q] = 0.f;

        const uint32_t* hb = (const uint32_t*)(hbuf + cur*16*132);
        #pragma unroll
        for (int kt = 0; kt < 8; kt++) {
            const int kp = kt*8;
            uint32_t a[4];
            a[0] = hb[(g  )*66 + kp + tq];
            a[1] = hb[(g+8)*66 + kp + tq];
            a[2] = hb[(g  )*66 + kp + tq + 4];
            a[3] = hb[(g+8)*66 + kp + tq + 4];
            #pragma unroll
            for (int fj = 0; fj < 2; fj++)
                mma_bf16(acc[fj], a, wb[fj][kt]);
        }
        #pragma unroll
        for (int fj = 0; fj < 2; fj++) {
            int nloc = w*16 + fj*8 + 2*tq;
            *(float2*)&zsm[g  ][nloc] = make_float2(acc[fj][0], acc[fj][1]);
            *(float2*)&zsm[g+8][nloc] = make_float2(acc[fj][2], acc[fj][3]);
        }

        if (s < 255) {
            cp_wait0();
            gproj((s+1) & 1, nxt);
        }
        __syncthreads();
        if (s < 253) xpre((s+1) & 1, dir ? (252 - s) : (s + 3));

        const float (*Gzc)[130] = Gz + cur*16;
        #pragma unroll
        for (int p2 = 0; p2 < 2; p2++) {
            int m = mh + p2;
            float ai = zsm[m][     jj] + Gzc[m][     jj] + bias_r[0];
            float af = zsm[m][32 + jj] + Gzc[m][32 + jj] + bias_r[1];
            float ag = zsm[m][64 + jj] + Gzc[m][64 + jj] + bias_r[2];
            float ao = zsm[m][96 + jj] + Gzc[m][96 + jj] + bias_r[3];
            float iv = sig_fast(ai);
            float fv = sig_fast(af);
            float gv = tanh_fast(ag);
            float ov = sig_fast(ao);
            c[p2] = fv*c[p2] + iv*gv;
            float hv = ov * tanh_fast(c[p2]);
            __nv_bfloat16 hb16 = __float2bfloat16(hv);
            g_hcat[(size_t)(nb0+m)*65536 + t*256 + dir*128 + jglob] = hb16;
            uint32_t off2 = (uint32_t)((nxt*16 + m)*132 + jglob) * 2u;
            hbuf[(nxt*16 + m)*132 + jglob] = hb16;
            unsigned short hu = *(unsigned short*)&hb16;
            asm volatile("st.shared::cluster.b16 [%0], %1;" :: "r"(rh[0] + off2), "h"(hu) : "memory");
            asm volatile("st.shared::cluster.b16 [%0], %1;" :: "r"(rh[1] + off2), "h"(hu) : "memory");
            asm volatile("st.shared::cluster.b16 [%0], %1;" :: "r"(rh[2] + off2), "h"(hu) : "memory");
        }

        asm volatile("mbarrier.arrive.release.cluster.shared::cta.b64 _, [%0];"
                     :: "r"(mbar_u32) : "memory");
        asm volatile("mbarrier.arrive.release.cluster.shared::cluster.b64 _, [%0];"
                     :: "r"(rm[0]) : "memory");
        asm volatile("mbarrier.arrive.release.cluster.shared::cluster.b64 _, [%0];"
                     :: "r"(rm[1]) : "memory");
        asm volatile("mbarrier.arrive.release.cluster.shared::cluster.b64 _, [%0];"
                     :: "r"(rm[2]) : "memory");
        {
            const uint32_t parity = (uint32_t)(s & 1);
            uint32_t done;
            asm volatile(
                "{\n\t.reg .pred p;\n\t"
                "mbarrier.try_wait.parity.acquire.cluster.shared::cta.b64 p, [%1], %2;\n\t"
                "selp.b32 %0, 1, 0, p;\n\t}"
                : "=r"(done) : "r"(mbar_u32), "r"(parity) : "memory");
            if (!done) {
                asm volatile(
                    "{\n\t.reg .pred P1;\n\t"
                    "WL_%=:\n\t"
                    "mbarrier.try_wait.parity.acquire.cluster.shared::cta.b64 P1, [%0], %1, 0x989680;\n\t"
                    "@P1 bra.uni WD_%=;\n\t"
                    "bra.uni WL_%=;\n\t"
                    "WD_%=:\n\t}"
                    :: "r"(mbar_u32), "r"(parity) : "memory");
            }
        }
    }
}

// ---------------------------------------------------------------------------
// FC1 split-K, bf16 mma, double-buffered (unchanged).
// ---------------------------------------------------------------------------
__global__ void fc1_mma_k()
{
    extern __shared__ uint32_t fsm[];
    uint32_t (*As)[20] = (uint32_t(*)[20])fsm;
    uint32_t (*Bs)[20] = (uint32_t(*)[20])(fsm + 2*256*20);

    const int tid  = threadIdx.x;
    const int lane = tid & 31;
    const int wid  = tid >> 5;
    const int g    = lane >> 2, tq = lane & 3;
    const int wm0  = (wid & 1) * 128;
    const int wn0  = (wid >> 1) * 32;
    const int k0   = blockIdx.x * 512;

    float acc[8][4][4];
    #pragma unroll
    for (int i = 0; i < 8; i++)
        #pragma unroll
        for (int j = 0; j < 4; j++)
            #pragma unroll
            for (int q = 0; q < 4; q++) acc[i][j][q] = 0.f;

    auto prefetch = [&](int b, int kt) {
        #pragma unroll
        for (int i = 0; i < 4; i++) {
            int l = i*256 + tid;
            int m = l >> 2, kq = l & 3;
            cp16(smem_u32(&As[b*256 + m][kq*4]),
                 g_hcat + (size_t)m*65536 + k0 + kt + kq*8);
        }
        #pragma unroll
        for (int i = 0; i < 2; i++) {
            int l = i*256 + tid;
            int n = l >> 2, kq = l & 3;
            cp16(smem_u32(&Bs[b*128 + n][kq*4]),
                 g_fc1wb16 + (size_t)n*65536 + k0 + kt + kq*8);
        }
    };

    prefetch(0, 0);
    cp_commit();
    cp_wait0();
    __syncthreads();

    for (int it = 0; it < 16; it++) {
        const int b = it & 1;
        if (it < 15) { prefetch(b^1, (it+1)*32); cp_commit(); }
        #pragma unroll
        for (int k16 = 0; k16 < 2; k16++) {
            const int kp = k16*8;
            uint32_t a[8][4], bb[4][2];
            #pragma unroll
            for (int fi = 0; fi < 8; fi++) {
                int r = b*256 + wm0 + fi*16;
                a[fi][0] = As[r+g  ][kp+tq];
                a[fi][1] = As[r+g+8][kp+tq];
                a[fi][2] = As[r+g  ][kp+tq+4];
                a[fi][3] = As[r+g+8][kp+tq+4];
            }
            #pragma unroll
            for (int fj = 0; fj < 4; fj++) {
                int cn = b*128 + wn0 + fj*8 + g;
                bb[fj][0] = Bs[cn][kp+tq];
                bb[fj][1] = Bs[cn][kp+tq+4];
            }
            #pragma unroll
            for (int fi = 0; fi < 8; fi++)
                #pragma unroll
                for (int fj = 0; fj < 4; fj++)
                    mma_bf16(acc[fi][fj], a[fi], bb[fj]);
        }
        if (it < 15) cp_wait0();
        __syncthreads();
    }

    float* part = g_fc1part + (size_t)blockIdx.x*256*128;
    #pragma unroll
    for (int fj = 0; fj < 4; fj++) {
        int n0 = wn0 + fj*8 + 2*tq;
        #pragma unroll
        for (int fi = 0; fi < 8; fi++) {
            #pragma unroll
            for (int p = 0; p < 2; p++) {
                int m = wm0 + fi*16 + g + p*8;
                *(float2*)(part + (size_t)m*128 + n0) =
                    make_float2(acc[fi][fj][p*2+0], acc[fi][fj][p*2+1]);
            }
        }
    }
}

__global__ void fc1_reduce_k(const float* __restrict__ fc1b)
{
    int idx = blockIdx.x*256 + threadIdx.x;
    int m = idx >> 7, h = idx & 127;
    float s = fc1b[h];
    #pragma unroll 8
    for (int kc = 0; kc < 128; kc++)
        s += g_fc1part[((size_t)kc*256 + m)*128 + h];
    g_z1[(size_t)m*128 + h] = fmaxf(s, 0.f);
}

__global__ void score_k(const float* __restrict__ fsw, const float* __restrict__ fsb,
                        float* __restrict__ out)
{
    __shared__ float w[128];
    __shared__ float fr[256];
    int tid = threadIdx.x;
    if (tid < 128) w[tid] = fsw[tid];
    __syncthreads();
    float acc = fsb[0];
    #pragma unroll 8
    for (int h = 0; h < 128; h++) acc += g_z1[(size_t)tid*128 + h] * w[h];
    float sc = 1.f / (1.f + expf(-acc)) * 4.f + 1.f;
    out[16 + tid] = sc;
    fr[tid] = sc;
    __syncthreads();
    if (tid < 16) {
        float s = 0.f;
        #pragma unroll
        for (int f = 0; f < 16; f++) s += fr[tid*16 + f];
        out[tid] = s * (1.f/16.f);
    }
}

// ---------------------------------------------------------------------------
extern "C" void kernel_launch(void* const* d_in, const int* in_sizes, int n_in,
                              void* d_out, int out_size)
{
    const float *audio,*w0,*b0,*w1,*b1,*w2,*b2,*w3,*b3;
    const float *Wihf,*Whhf,*bihf,*bhhf,*Wihb,*Whhb,*bihb,*bhhb;
    const float *fc1w,*fc1b,*fsw,*fsb;
    if (n_in >= 22 && in_sizes[1] == 144) {
        audio=(const float*)d_in[0];
        w0=(const float*)d_in[1];  b0=(const float*)d_in[2];
        w1=(const float*)d_in[3];  b1=(const float*)d_in[4];
        w2=(const float*)d_in[5];  b2=(const float*)d_in[6];
        w3=(const float*)d_in[7];  b3=(const float*)d_in[8];
        Wihf=(const float*)d_in[9];  Whhf=(const float*)d_in[10];
        bihf=(const float*)d_in[11]; bhhf=(const float*)d_in[12];
        Wihb=(const float*)d_in[13]; Whhb=(const float*)d_in[14];
        bihb=(const float*)d_in[15]; bhhb=(const float*)d_in[16];
        fc1w=(const float*)d_in[17]; fc1b=(const float*)d_in[18];
        fsw=(const float*)d_in[19];  fsb=(const float*)d_in[20];
    } else {
        audio=(const float*)d_in[0];
        w0=(const float*)d_in[2];  b0=(const float*)d_in[3];
        w1=(const float*)d_in[4];  b1=(const float*)d_in[5];
        w2=(const float*)d_in[6];  b2=(const float*)d_in[7];
        w3=(const float*)d_in[8];  b3=(const float*)d_in[9];
        Wihf=(const float*)d_in[10]; Whhf=(const float*)d_in[11];
        bihf=(const float*)d_in[12]; bhhf=(const float*)d_in[13];
        Wihb=(const float*)d_in[14]; Whhb=(const float*)d_in[15];
        bihb=(const float*)d_in[16]; bhhb=(const float*)d_in[17];
        fc1w=(const float*)d_in[18]; fc1b=(const float*)d_in[19];
        fsw=(const float*)d_in[20];  fsb=(const float*)d_in[21];
    }

    __nv_bfloat16 *x0,*x1,*x2,*xT,*wT1,*wT2,*wT3;
    cudaGetSymbolAddress((void**)&x0, g_x0);
    cudaGetSymbolAddress((void**)&x1, g_x1);
    cudaGetSymbolAddress((void**)&x2, g_x2);
    cudaGetSymbolAddress((void**)&xT, g_xT);
    cudaGetSymbolAddress((void**)&wT1, g_wT1);
    cudaGetSymbolAddress((void**)&wT2, g_wT2);
    cudaGetSymbolAddress((void**)&wT3, g_wT3);

    // conv smem: (BM+2)*LDT*4 + NTAP*CBLK*LDB*4
    const int sc1 = (66*(27*8 +4) + 9*32*(8 +4))*4;     // 71,904
    const int sc2 = (66*(9*16 +4) + 9*64*(16+4))*4;     // 85,152
    const int sc3 = (66*(3*32 +4) + 6*64*(32+4))*4;     // 81,696
    const int sf  = 2*(256 + 128)*20*4;
    const int slm = 42120;
    cudaFuncSetAttribute((void*)conv_mma_k<16, 32,27,9,64,2,16,0,2,1,false>, cudaFuncAttributeMaxDynamicSharedMemorySize, sc1);
    cudaFuncSetAttribute((void*)conv_mma_k<32, 64, 9,3,64,2,32,0,2,1,false>, cudaFuncAttributeMaxDynamicSharedMemorySize, sc2);
    cudaFuncSetAttribute((void*)conv_mma_k<64,128, 3,1,64,2,32,1,2,2,true >, cudaFuncAttributeMaxDynamicSharedMemorySize, sc3);
    cudaFuncSetAttribute(fc1_mma_k, cudaFuncAttributeMaxDynamicSharedMemorySize, sf);
    cudaFuncSetAttribute(lstm_k, cudaFuncAttributeMaxDynamicSharedMemorySize, slm);

    wtrans_k<<<(96768 + 255)/256, 256>>>(w1, w2, w3);
    prep_bf16_k<<<4096, 256>>>(fc1w);

    conv0_k<<<(BF*NT*27)/256, 256>>>(audio, w0, b0, x0);
    conv_mma_k<16, 32,27,9,64,2,16,0,2,1,false><<<dim3(4,BF),   256, sc1>>>(x0, wT1, b1, x1);
    conv_mma_k<32, 64, 9,3,64,2,32,0,2,1,false><<<dim3(4,BF),   256, sc2>>>(x1, wT2, b2, x2);
    conv_mma_k<64,128, 3,1,64,2,32,1,2,2,true ><<<dim3(4,2,BF), 256, sc3>>>(x2, wT3, b3, xT);

    lstm_k<<<dim3(4,16,2), 256, slm>>>(Whhf, Whhb, Wihf, Wihb,
                                       bihf, bhhf, bihb, bhhb);

    fc1_mma_k<<<128, 256, sf>>>();
    fc1_reduce_k<<<128, 256>>>(fc1b);
    score_k<<<1, 256>>>(fsw, fsb, (float*)d_out);
}